// round 12
// baseline (speedup 1.0000x reference)
#include <cuda_runtime.h>
#include <cuda_bf16.h>
#include <cuda_fp16.h>
#include <math.h>

#define NN 50000
#define EE 1250000
#define HH 128
#define LL 64
#define NSTEPS 5
#define EPSV 1e-6f
#define SMSHIFT 30.0f

#define ETROWS 256
#define NTROWS 256

#define W0F_U (4 * 16 * 32 * 4)
#define W1F_U (8 * 16 * 32 * 4)
#define W2F_U (8 * 8 * 32 * 4)
#define WSTEP_U (W0F_U + W1F_U + W2F_U)

// ---------------- device scratch ----------------
__device__ __half2 g_elat[(size_t)EE * 32];   // edge latents fp16 (160 MB)
__device__ float g_n[NN * LL];
__device__ float g_x[NN * LL];
__device__ int   g_deg[NN];
__device__ int   g_rowstart[NN + 1];
__device__ int   g_cursor[NN];
__device__ int2  g_epair[EE];                 // CSR slot -> (edge id, sender)
__device__ unsigned g_wfrag[NSTEPS * WSTEP_U];

// ---------------- CSR build ----------------
__global__ void degree_kernel(const int* __restrict__ receivers) {
    int e = blockIdx.x * blockDim.x + threadIdx.x;
    if (e < EE) atomicAdd(&g_deg[receivers[e]], 1);
}
__global__ void scan_kernel() {
    __shared__ int ssum[1024];
    const int tid = threadIdx.x;
    const int chunk = (NN + 1023) / 1024;
    const int start = tid * chunk;
    const int cend = min(start + chunk, NN);
    int sum = 0;
    for (int i = start; i < cend; i++) sum += g_deg[i];
    ssum[tid] = sum;
    __syncthreads();
    if (tid == 0) {
        int run = 0;
        for (int i = 0; i < 1024; i++) { int v = ssum[i]; ssum[i] = run; run += v; }
        g_rowstart[NN] = run;
    }
    __syncthreads();
    int run = ssum[tid];
    for (int i = start; i < cend; i++) {
        g_rowstart[i] = run;
        g_cursor[i] = run;
        run += g_deg[i];
    }
}
__global__ void scatter_kernel(const int* __restrict__ receivers,
                               const int* __restrict__ senders) {
    int e = blockIdx.x * blockDim.x + threadIdx.x;
    if (e < EE) {
        int r = receivers[e];
        int p = atomicAdd(&g_cursor[r], 1);
        g_epair[p] = make_int2(e, senders[e]);
    }
}

// ---------------- bf16 split + mma helpers ----------------
__device__ __forceinline__ void split2(float a, float b, unsigned& hi, unsigned& lo) {
    __nv_bfloat16 ha = __float2bfloat16(a);
    __nv_bfloat16 hb = __float2bfloat16(b);
    float la = a - __bfloat162float(ha);
    float lb = b - __bfloat162float(hb);
    __nv_bfloat162 ph; ph.x = ha; ph.y = hb;
    __nv_bfloat162 pl = __floats2bfloat162_rn(la, lb);
    hi = *(unsigned*)&ph;
    lo = *(unsigned*)&pl;
}

__device__ __forceinline__ void mma_bf16(float* d, uint4 a, uint2 b) {
    asm volatile(
        "mma.sync.aligned.m16n8k16.row.col.f32.bf16.bf16.f32 "
        "{%0,%1,%2,%3}, {%4,%5,%6,%7}, {%8,%9}, {%0,%1,%2,%3};\n"
        : "+f"(d[0]), "+f"(d[1]), "+f"(d[2]), "+f"(d[3])
        : "r"(a.x), "r"(a.y), "r"(a.z), "r"(a.w), "r"(b.x), "r"(b.y));
}

__device__ __forceinline__ void mma3(float* d, uint4 ah, uint4 al, uint4 q) {
    uint2 bh = make_uint2(q.x, q.y);
    uint2 bl = make_uint2(q.z, q.w);
    mma_bf16(d, ah, bh);
    mma_bf16(d, ah, bl);
    mma_bf16(d, al, bh);
}

__device__ __forceinline__ void stage_bfrag_g(
    const float* __restrict__ W, int ncols, int KT, int NT, unsigned* dst,
    int tid, int nthreads)
{
    int total = KT * NT * 64;
    for (int idx = tid; idx < total; idx += nthreads) {
        int reg = idx & 1;
        int ln  = (idx >> 1) & 31;
        int fnt = (idx >> 6) % NT;
        int fkt = (idx >> 6) / NT;
        int k = fkt * 16 + reg * 8 + (ln & 3) * 2;
        int n = fnt * 8 + (ln >> 2);
        unsigned hi, lo;
        split2(__ldg(W + k * ncols + n), __ldg(W + (k + 1) * ncols + n), hi, lo);
        unsigned* cell = dst + ((size_t)(fkt * NT + fnt) * 32 + ln) * 4;
        cell[reg]     = hi;
        cell[2 + reg] = lo;
    }
}

// grid (NSTEPS, CHUNKS): parallel weight-fragment conversion
#define PREP_CHUNKS 8
__global__ void prep_wfrag_kernel(const float* __restrict__ pW0,
                                  const float* __restrict__ pW1,
                                  const float* __restrict__ pW2)
{
    int s = blockIdx.x;
    int tid = blockIdx.y * blockDim.x + threadIdx.x;
    int nth = PREP_CHUNKS * blockDim.x;
    unsigned* dst = g_wfrag + (size_t)s * WSTEP_U;
    stage_bfrag_g(pW0 + (size_t)s * LL * HH, HH, 4, 16, dst, tid, nth);
    stage_bfrag_g(pW1 + (size_t)s * HH * HH, HH, 8, 16, dst + W0F_U, tid, nth);
    stage_bfrag_g(pW2 + (size_t)s * HH * LL, LL, 8, 8,  dst + W0F_U + W1F_U, tid, nth);
}

// ---------------- tensor-core edge encoder: 3 -> 128 -> 128 -> 64 (fp16 out) ----------------
__global__ void __launch_bounds__(ETROWS, 1) edge_encoder_tc(
    const float* __restrict__ edges,
    const float* __restrict__ W0, const float* __restrict__ B0,
    const float* __restrict__ W1, const float* __restrict__ B1,
    const float* __restrict__ W2, const float* __restrict__ B2,
    __half2* __restrict__ Y)
{
    extern __shared__ unsigned smu[];
    unsigned* B1f = smu;
    unsigned* B2f = B1f + 8 * 16 * 32 * 4;

    const int tid  = threadIdx.x;
    const int lane = tid & 31;
    const int warp = tid >> 5;
    const int cbase = (lane & 3) * 2;

    stage_bfrag_g(W1, HH, 8, 16, B1f, tid, ETROWS);
    stage_bfrag_g(W2, LL, 8, 8,  B2f, tid, ETROWS);
    __syncthreads();

    float2 b1c[16], b2c[8];
#pragma unroll
    for (int nt = 0; nt < 16; nt++) b1c[nt] = __ldg((const float2*)(B1 + nt * 8 + cbase));
#pragma unroll
    for (int nt = 0; nt < 8;  nt++) b2c[nt] = __ldg((const float2*)(B2 + nt * 8 + cbase));

    const int ntiles = (EE + ETROWS - 1) / ETROWS;
    for (int tile = blockIdx.x; tile < ntiles; tile += gridDim.x) {
        const int row0 = tile * ETROWS;
        const int rb = row0 + warp * 32 + (lane >> 2);

        float xr[4][3];
#pragma unroll
        for (int j = 0; j < 4; j++) {
            int gr = rb + j * 8;
            bool ok = (gr < EE);
            const float* p = edges + (size_t)gr * 3;
            xr[j][0] = ok ? __ldg(p)     : 0.f;
            xr[j][1] = ok ? __ldg(p + 1) : 0.f;
            xr[j][2] = ok ? __ldg(p + 2) : 0.f;
        }

        float acc1[2][16][4];
#pragma unroll
        for (int nt = 0; nt < 16; nt++) {
#pragma unroll
            for (int mt = 0; mt < 2; mt++) {
                acc1[mt][nt][0] = b1c[nt].x; acc1[mt][nt][1] = b1c[nt].y;
                acc1[mt][nt][2] = b1c[nt].x; acc1[mt][nt][3] = b1c[nt].y;
            }
        }
#pragma unroll
        for (int kt = 0; kt < 8; kt++) {
            float v[4][4];
#pragma unroll
            for (int cc = 0; cc < 4; cc++) {
                int col = kt * 16 + cbase + (cc & 1) + ((cc >> 1) << 3);
                float w0v = __ldg(W0 + col);
                float w1v = __ldg(W0 + HH + col);
                float w2v = __ldg(W0 + 2 * HH + col);
                float bb  = __ldg(B0 + col);
#pragma unroll
                for (int j = 0; j < 4; j++) {
                    float t = fmaf(xr[j][2], w2v, fmaf(xr[j][1], w1v, fmaf(xr[j][0], w0v, bb)));
                    v[j][cc] = fmaxf(t, 0.f);
                }
            }
            uint4 AH[2], AL[2];
#pragma unroll
            for (int mt = 0; mt < 2; mt++) {
                split2(v[2 * mt][0],     v[2 * mt][1],     AH[mt].x, AL[mt].x);
                split2(v[2 * mt + 1][0], v[2 * mt + 1][1], AH[mt].y, AL[mt].y);
                split2(v[2 * mt][2],     v[2 * mt][3],     AH[mt].z, AL[mt].z);
                split2(v[2 * mt + 1][2], v[2 * mt + 1][3], AH[mt].w, AL[mt].w);
            }
#pragma unroll
            for (int nt = 0; nt < 16; nt++) {
                uint4 q = *(const uint4*)(B1f + ((size_t)(kt * 16 + nt) * 32 + lane) * 4);
                mma3(acc1[0][nt], AH[0], AL[0], q);
                mma3(acc1[1][nt], AH[1], AL[1], q);
            }
        }

        unsigned A2h[2][8][4], A2l[2][8][4];
#pragma unroll
        for (int mt = 0; mt < 2; mt++) {
#pragma unroll
            for (int nt = 0; nt < 16; nt++) {
                int kt2 = nt >> 1, half = (nt & 1) * 2;
                split2(fmaxf(acc1[mt][nt][0], 0.f), fmaxf(acc1[mt][nt][1], 0.f),
                       A2h[mt][kt2][half], A2l[mt][kt2][half]);
                split2(fmaxf(acc1[mt][nt][2], 0.f), fmaxf(acc1[mt][nt][3], 0.f),
                       A2h[mt][kt2][half + 1], A2l[mt][kt2][half + 1]);
            }
        }

        float acc2[2][8][4];
#pragma unroll
        for (int nt = 0; nt < 8; nt++) {
#pragma unroll
            for (int mt = 0; mt < 2; mt++) {
                acc2[mt][nt][0] = b2c[nt].x; acc2[mt][nt][1] = b2c[nt].y;
                acc2[mt][nt][2] = b2c[nt].x; acc2[mt][nt][3] = b2c[nt].y;
            }
        }
#pragma unroll
        for (int kt = 0; kt < 8; kt++) {
            uint4 a2h0 = make_uint4(A2h[0][kt][0], A2h[0][kt][1], A2h[0][kt][2], A2h[0][kt][3]);
            uint4 a2l0 = make_uint4(A2l[0][kt][0], A2l[0][kt][1], A2l[0][kt][2], A2l[0][kt][3]);
            uint4 a2h1 = make_uint4(A2h[1][kt][0], A2h[1][kt][1], A2h[1][kt][2], A2h[1][kt][3]);
            uint4 a2l1 = make_uint4(A2l[1][kt][0], A2l[1][kt][1], A2l[1][kt][2], A2l[1][kt][3]);
#pragma unroll
            for (int nt = 0; nt < 8; nt++) {
                uint4 q = *(const uint4*)(B2f + ((size_t)(kt * 8 + nt) * 32 + lane) * 4);
                mma3(acc2[0][nt], a2h0, a2l0, q);
                mma3(acc2[1][nt], a2h1, a2l1, q);
            }
        }

#pragma unroll
        for (int mt = 0; mt < 2; mt++) {
            int r0g = row0 + warp * 32 + mt * 16 + (lane >> 2);
            int r1g = r0g + 8;
#pragma unroll
            for (int nt = 0; nt < 8; nt++) {
                int cid = nt * 4 + (lane & 3);
                if (r0g < EE)
                    Y[(size_t)r0g * 32 + cid] = __floats2half2_rn(acc2[mt][nt][0], acc2[mt][nt][1]);
                if (r1g < EE)
                    Y[(size_t)r1g * 32 + cid] = __floats2half2_rn(acc2[mt][nt][2], acc2[mt][nt][3]);
            }
        }
    }
}

// ---------------- tensor-core node-step MLP: 64 -> 128 -> 128 -> 64 ----------------
__global__ void __launch_bounds__(NTROWS, 1) node_mlp_tc(
    const float* __restrict__ X,
    int step,
    const float* __restrict__ B0,
    const float* __restrict__ B1,
    const float* __restrict__ B2,
    float* __restrict__ Y)
{
    extern __shared__ unsigned smu[];
    unsigned* W0f = smu;
    unsigned* W1f = W0f + W0F_U;
    unsigned* W2f = W1f + W1F_U;

    {
        const uint4* src = (const uint4*)(g_wfrag + (size_t)step * WSTEP_U);
        uint4* dst = (uint4*)smu;
        for (int i = threadIdx.x; i < WSTEP_U / 4; i += NTROWS) dst[i] = __ldg(src + i);
    }
    __syncthreads();

    const int lane = threadIdx.x & 31;
    const int warp = threadIdx.x >> 5;
    const int cbase = (lane & 3) * 2;
    const int g0 = blockIdx.x * NTROWS + warp * 32 + (lane >> 2);

    float acc1[2][16][4];
#pragma unroll
    for (int nt = 0; nt < 16; nt++) {
        float2 b = __ldg((const float2*)(B0 + nt * 8 + cbase));
#pragma unroll
        for (int mt = 0; mt < 2; mt++) {
            acc1[mt][nt][0] = b.x; acc1[mt][nt][1] = b.y;
            acc1[mt][nt][2] = b.x; acc1[mt][nt][3] = b.y;
        }
    }
#pragma unroll
    for (int kt = 0; kt < 4; kt++) {
        uint4 AH[2], AL[2];
#pragma unroll
        for (int mt = 0; mt < 2; mt++) {
            int ga = g0 + mt * 16, gb = ga + 8;
            float2 z = make_float2(0.f, 0.f);
            float2 p0 = (ga < NN) ? *(const float2*)(X + (size_t)ga * LL + kt * 16 + cbase)     : z;
            float2 p1 = (gb < NN) ? *(const float2*)(X + (size_t)gb * LL + kt * 16 + cbase)     : z;
            float2 p2 = (ga < NN) ? *(const float2*)(X + (size_t)ga * LL + kt * 16 + cbase + 8) : z;
            float2 p3 = (gb < NN) ? *(const float2*)(X + (size_t)gb * LL + kt * 16 + cbase + 8) : z;
            split2(p0.x, p0.y, AH[mt].x, AL[mt].x);
            split2(p1.x, p1.y, AH[mt].y, AL[mt].y);
            split2(p2.x, p2.y, AH[mt].z, AL[mt].z);
            split2(p3.x, p3.y, AH[mt].w, AL[mt].w);
        }
#pragma unroll
        for (int nt = 0; nt < 16; nt++) {
            uint4 q = *(const uint4*)(W0f + ((size_t)(kt * 16 + nt) * 32 + lane) * 4);
            mma3(acc1[0][nt], AH[0], AL[0], q);
            mma3(acc1[1][nt], AH[1], AL[1], q);
        }
    }

    unsigned A2h[2][8][4], A2l[2][8][4];
#pragma unroll
    for (int mt = 0; mt < 2; mt++) {
        unsigned A1h[8][4], A1l[8][4];
#pragma unroll
        for (int nt = 0; nt < 16; nt++) {
            int kt2 = nt >> 1, half = (nt & 1) * 2;
            split2(fmaxf(acc1[mt][nt][0], 0.f), fmaxf(acc1[mt][nt][1], 0.f),
                   A1h[kt2][half], A1l[kt2][half]);
            split2(fmaxf(acc1[mt][nt][2], 0.f), fmaxf(acc1[mt][nt][3], 0.f),
                   A1h[kt2][half + 1], A1l[kt2][half + 1]);
        }
        float accB[16][4];
#pragma unroll
        for (int nt = 0; nt < 16; nt++) {
            float2 b = __ldg((const float2*)(B1 + nt * 8 + cbase));
            accB[nt][0] = b.x; accB[nt][1] = b.y; accB[nt][2] = b.x; accB[nt][3] = b.y;
        }
#pragma unroll
        for (int kt = 0; kt < 8; kt++) {
            uint4 ah = make_uint4(A1h[kt][0], A1h[kt][1], A1h[kt][2], A1h[kt][3]);
            uint4 al = make_uint4(A1l[kt][0], A1l[kt][1], A1l[kt][2], A1l[kt][3]);
#pragma unroll
            for (int nt = 0; nt < 16; nt++) {
                uint4 q = *(const uint4*)(W1f + ((size_t)(kt * 16 + nt) * 32 + lane) * 4);
                mma3(accB[nt], ah, al, q);
            }
        }
#pragma unroll
        for (int nt = 0; nt < 16; nt++) {
            int kt2 = nt >> 1, half = (nt & 1) * 2;
            split2(fmaxf(accB[nt][0], 0.f), fmaxf(accB[nt][1], 0.f),
                   A2h[mt][kt2][half], A2l[mt][kt2][half]);
            split2(fmaxf(accB[nt][2], 0.f), fmaxf(accB[nt][3], 0.f),
                   A2h[mt][kt2][half + 1], A2l[mt][kt2][half + 1]);
        }
    }

    float acc2[2][8][4];
#pragma unroll
    for (int nt = 0; nt < 8; nt++) {
        float2 b = __ldg((const float2*)(B2 + nt * 8 + cbase));
#pragma unroll
        for (int mt = 0; mt < 2; mt++) {
            acc2[mt][nt][0] = b.x; acc2[mt][nt][1] = b.y;
            acc2[mt][nt][2] = b.x; acc2[mt][nt][3] = b.y;
        }
    }
#pragma unroll
    for (int kt = 0; kt < 8; kt++) {
        uint4 a2h0 = make_uint4(A2h[0][kt][0], A2h[0][kt][1], A2h[0][kt][2], A2h[0][kt][3]);
        uint4 a2l0 = make_uint4(A2l[0][kt][0], A2l[0][kt][1], A2l[0][kt][2], A2l[0][kt][3]);
        uint4 a2h1 = make_uint4(A2h[1][kt][0], A2h[1][kt][1], A2h[1][kt][2], A2h[1][kt][3]);
        uint4 a2l1 = make_uint4(A2l[1][kt][0], A2l[1][kt][1], A2l[1][kt][2], A2l[1][kt][3]);
#pragma unroll
        for (int nt = 0; nt < 8; nt++) {
            uint4 q = *(const uint4*)(W2f + ((size_t)(kt * 8 + nt) * 32 + lane) * 4);
            mma3(acc2[0][nt], a2h0, a2l0, q);
            mma3(acc2[1][nt], a2h1, a2l1, q);
        }
    }

#pragma unroll
    for (int mt = 0; mt < 2; mt++) {
        int ga = g0 + mt * 16, gb = ga + 8;
#pragma unroll
        for (int nt = 0; nt < 8; nt++) {
            int colg = nt * 8 + cbase;
            if (ga < NN) {
                float2 o; o.x = acc2[mt][nt][0]; o.y = acc2[mt][nt][1];
                *(float2*)&Y[(size_t)ga * LL + colg] = o;
            }
            if (gb < NN) {
                float2 o; o.x = acc2[mt][nt][2]; o.y = acc2[mt][nt][3];
                *(float2*)&Y[(size_t)gb * LL + colg] = o;
            }
        }
    }
}

// ---------------- fused FFMA MLP (node encoder + decoder) ----------------
template <int IN, int OUT>
__global__ void __launch_bounds__(256) mlp3_kernel(
    const float* __restrict__ X,
    const float* __restrict__ W0, const float* __restrict__ B0,
    const float* __restrict__ W1, const float* __restrict__ B1,
    const float* __restrict__ W2, const float* __restrict__ B2,
    float* __restrict__ Y, int nrows,
    const float* __restrict__ mask_src)
{
    constexpr int RPW = 4;
    __shared__ float sh_h[8][HH * RPW];
    __shared__ float sh_x[8][IN * RPW];
    const int warp = threadIdx.x >> 5;
    const int lane = threadIdx.x & 31;
    const int row0 = (blockIdx.x * 8 + warp) * RPW;
    if (row0 >= nrows) return;
    float* hx = sh_x[warp];
    float* hh = sh_h[warp];

    for (int i = lane; i < IN; i += 32) {
#pragma unroll
        for (int r = 0; r < RPW; r++) {
            int row = row0 + r;
            hx[i * RPW + r] = (row < nrows) ? X[(size_t)row * IN + i] : 0.f;
        }
    }
    __syncwarp();

    const int j0 = lane << 2;
    float acc[RPW][4];
    {
        float4 b = *(const float4*)(B0 + j0);
#pragma unroll
        for (int r = 0; r < RPW; r++) { acc[r][0] = b.x; acc[r][1] = b.y; acc[r][2] = b.z; acc[r][3] = b.w; }
#pragma unroll
        for (int i = 0; i < IN; i++) {
            float4 w = __ldg((const float4*)(W0 + i * HH + j0));
#pragma unroll
            for (int r = 0; r < RPW; r++) {
                float xv = hx[i * RPW + r];
                acc[r][0] += xv * w.x; acc[r][1] += xv * w.y;
                acc[r][2] += xv * w.z; acc[r][3] += xv * w.w;
            }
        }
    }
#pragma unroll
    for (int jj = 0; jj < 4; jj++) {
        float4 v = make_float4(fmaxf(acc[0][jj], 0.f), fmaxf(acc[1][jj], 0.f),
                               fmaxf(acc[2][jj], 0.f), fmaxf(acc[3][jj], 0.f));
        *(float4*)(hh + (j0 + jj) * RPW) = v;
    }
    __syncwarp();
    {
        float4 b = *(const float4*)(B1 + j0);
#pragma unroll
        for (int r = 0; r < RPW; r++) { acc[r][0] = b.x; acc[r][1] = b.y; acc[r][2] = b.z; acc[r][3] = b.w; }
#pragma unroll 4
        for (int k = 0; k < HH; k++) {
            float4 w = __ldg((const float4*)(W1 + k * HH + j0));
            float4 hv = *(const float4*)(hh + k * RPW);
            acc[0][0] += hv.x * w.x; acc[0][1] += hv.x * w.y; acc[0][2] += hv.x * w.z; acc[0][3] += hv.x * w.w;
            acc[1][0] += hv.y * w.x; acc[1][1] += hv.y * w.y; acc[1][2] += hv.y * w.z; acc[1][3] += hv.y * w.w;
            acc[2][0] += hv.z * w.x; acc[2][1] += hv.z * w.y; acc[2][2] += hv.z * w.z; acc[2][3] += hv.z * w.w;
            acc[3][0] += hv.w * w.x; acc[3][1] += hv.w * w.y; acc[3][2] += hv.w * w.z; acc[3][3] += hv.w * w.w;
        }
    }
    __syncwarp();
#pragma unroll
    for (int jj = 0; jj < 4; jj++) {
        float4 v = make_float4(fmaxf(acc[0][jj], 0.f), fmaxf(acc[1][jj], 0.f),
                               fmaxf(acc[2][jj], 0.f), fmaxf(acc[3][jj], 0.f));
        *(float4*)(hh + (j0 + jj) * RPW) = v;
    }
    __syncwarp();

    constexpr int JV = (OUT >= 32) ? (OUT / 32) : 1;
    const int j2 = (OUT >= 32) ? lane * JV : lane;
    const bool act2 = (OUT >= 32) ? true : (lane < OUT);
    float a3[RPW][JV];
#pragma unroll
    for (int r = 0; r < RPW; r++)
#pragma unroll
        for (int jj = 0; jj < JV; jj++) a3[r][jj] = act2 ? B2[j2 + jj] : 0.f;

#pragma unroll 4
    for (int k = 0; k < HH; k++) {
        float4 hv = *(const float4*)(hh + k * RPW);
        if constexpr (JV == 2) {
            float2 w = __ldg((const float2*)(W2 + k * OUT + j2));
            a3[0][0] += hv.x * w.x; a3[0][1] += hv.x * w.y;
            a3[1][0] += hv.y * w.x; a3[1][1] += hv.y * w.y;
            a3[2][0] += hv.z * w.x; a3[2][1] += hv.z * w.y;
            a3[3][0] += hv.w * w.x; a3[3][1] += hv.w * w.y;
        } else {
            if (act2) {
                float w = __ldg(W2 + k * OUT + j2);
                a3[0][0] += hv.x * w; a3[1][0] += hv.y * w;
                a3[2][0] += hv.z * w; a3[3][0] += hv.w * w;
            }
        }
    }
#pragma unroll
    for (int r = 0; r < RPW; r++) {
        int row = row0 + r;
        if (row < nrows && act2) {
            float mk = 1.f;
            if (mask_src) {
                mk = ((fabsf(mask_src[row * 2]) + fabsf(mask_src[row * 2 + 1])) != 0.f) ? 1.f : 0.f;
            }
#pragma unroll
            for (int jj = 0; jj < JV; jj++)
                Y[(size_t)row * OUT + j2 + jj] = a3[r][jj] * mk;
        }
    }
}

// ---------------- softmax aggregation: fp16 elat, fp32 nin, 8-wide strip + index prefetch ----------------
__global__ void __launch_bounds__(256) agg_kernel(
    const float* __restrict__ nin,
    float* __restrict__ xout)
{
    const int gw = (blockIdx.x * blockDim.x + threadIdx.x) >> 5;
    if (gw >= NN) return;
    const int lane = threadIdx.x & 31;
    const int beg = __ldg(g_rowstart + gw);
    const int end = __ldg(g_rowstart + gw + 1);

    const float2* nin2 = (const float2*)nin;
    float S0 = 0.f, S1 = 0.f, A0 = 0.f, A1 = 0.f;

    int idx = beg;
    int nfull = (end - beg) / 8;

    if (nfull > 0) {
        int2 pr[8];
#pragma unroll
        for (int u = 0; u < 8; u++) pr[u] = __ldg(g_epair + idx + u);

        for (int it = 0; it < nfull; it++) {
            float2 ev[8], nv[8];
#pragma unroll
            for (int u = 0; u < 8; u++)
                ev[u] = __half22float2(__ldg(g_elat + (size_t)pr[u].x * 32 + lane));
#pragma unroll
            for (int u = 0; u < 8; u++)
                nv[u] = __ldg(nin2 + (size_t)pr[u].y * 32 + lane);

            // prefetch next strip's indices before the math tail
            int nidx = idx + 8;
            int2 nx[8];
            if (it + 1 < nfull) {
#pragma unroll
                for (int u = 0; u < 8; u++) nx[u] = __ldg(g_epair + nidx + u);
            }

#pragma unroll
            for (int u = 0; u < 8; u++) {
                float m0 = fmaxf(ev[u].x + nv[u].x, 0.f) + EPSV;
                float m1 = fmaxf(ev[u].y + nv[u].y, 0.f) + EPSV;
                float t0 = __expf(m0 - SMSHIFT);
                float t1 = __expf(m1 - SMSHIFT);
                S0 += t0; A0 = fmaf(t0, m0, A0);
                S1 += t1; A1 = fmaf(t1, m1, A1);
            }
            if (it + 1 < nfull) {
#pragma unroll
                for (int u = 0; u < 8; u++) pr[u] = nx[u];
            }
            idx = nidx;
        }
    }
    for (; idx < end; idx++) {
        int2 pr = __ldg(g_epair + idx);
        float2 ea = __half22float2(__ldg(g_elat + (size_t)pr.x * 32 + lane));
        float2 na = __ldg(nin2 + (size_t)pr.y * 32 + lane);
        float m0 = fmaxf(ea.x + na.x, 0.f) + EPSV;
        float m1 = fmaxf(ea.y + na.y, 0.f) + EPSV;
        float t0 = __expf(m0 - SMSHIFT);
        float t1 = __expf(m1 - SMSHIFT);
        S0 += t0; A0 = fmaf(t0, m0, A0);
        S1 += t1; A1 = fmaf(t1, m1, A1);
    }

    float r0 = (S0 > 0.f) ? A0 / S0 : 0.f;
    float r1 = (S1 > 0.f) ? A1 / S1 : 0.f;
    float2 ns = __ldg(nin2 + (size_t)gw * 32 + lane);
    float2 o; o.x = ns.x + r0; o.y = ns.y + r1;
    *((float2*)xout + (size_t)gw * 32 + lane) = o;
}

// ---------------- launch ----------------
extern "C" void kernel_launch(void* const* d_in, const int* in_sizes, int n_in,
                              void* d_out, int out_size)
{
    const float* nodes     = (const float*)d_in[0];
    const float* edges     = (const float*)d_in[1];
    const int*   senders   = (const int*)  d_in[2];
    const int*   receivers = (const int*)  d_in[3];
    const float* enW0 = (const float*)d_in[4];  const float* enb0 = (const float*)d_in[5];
    const float* enW1 = (const float*)d_in[6];  const float* enb1 = (const float*)d_in[7];
    const float* enW2 = (const float*)d_in[8];  const float* enb2 = (const float*)d_in[9];
    const float* eeW0 = (const float*)d_in[10]; const float* eeb0 = (const float*)d_in[11];
    const float* eeW1 = (const float*)d_in[12]; const float* eeb1 = (const float*)d_in[13];
    const float* eeW2 = (const float*)d_in[14]; const float* eeb2 = (const float*)d_in[15];
    const float* pW0  = (const float*)d_in[16]; const float* pb0  = (const float*)d_in[17];
    const float* pW1  = (const float*)d_in[18]; const float* pb1  = (const float*)d_in[19];
    const float* pW2  = (const float*)d_in[20]; const float* pb2  = (const float*)d_in[21];
    const float* dW0  = (const float*)d_in[22]; const float* db0  = (const float*)d_in[23];
    const float* dW1  = (const float*)d_in[24]; const float* db1  = (const float*)d_in[25];
    const float* dW2  = (const float*)d_in[26]; const float* db2  = (const float*)d_in[27];
    float* out = (float*)d_out;

    __half2* p_elat = nullptr;
    float *p_n = nullptr, *p_x = nullptr;
    int* p_deg = nullptr;
    cudaGetSymbolAddress((void**)&p_elat, g_elat);
    cudaGetSymbolAddress((void**)&p_n,    g_n);
    cudaGetSymbolAddress((void**)&p_x,    g_x);
    cudaGetSymbolAddress((void**)&p_deg,  g_deg);

    // CSR build
    cudaMemsetAsync(p_deg, 0, NN * sizeof(int));
    degree_kernel<<<(EE + 255) / 256, 256>>>(receivers);
    scan_kernel<<<1, 1024>>>();
    scatter_kernel<<<(EE + 255) / 256, 256>>>(receivers, senders);

    // pre-convert step-MLP weights (parallel)
    {
        dim3 pgrid(NSTEPS, PREP_CHUNKS);
        prep_wfrag_kernel<<<pgrid, 256>>>(pW0, pW1, pW2);
    }

    // node encoder (FFMA)
    mlp3_kernel<2, 64><<<(NN + 31) / 32, 256>>>(
        nodes, enW0, enb0, enW1, enb1, enW2, enb2, p_n, NN, nullptr);

    // edge encoder (tensor cores, fp16 output)
    {
        const int smem = (8 * 16 * 32 * 4 + 8 * 8 * 32 * 4) * 4;
        cudaFuncSetAttribute(edge_encoder_tc,
                             cudaFuncAttributeMaxDynamicSharedMemorySize, smem);
        edge_encoder_tc<<<148, ETROWS, smem>>>(
            edges, eeW0, eeb0, eeW1, eeb1, eeW2, eeb2, p_elat);
    }

    // processor steps
    const int aggBlocks = (NN * 32 + 255) / 256;
    const int nodeSmem = WSTEP_U * 4;
    cudaFuncSetAttribute(node_mlp_tc,
                         cudaFuncAttributeMaxDynamicSharedMemorySize, nodeSmem);
    const int nodeBlocks = (NN + NTROWS - 1) / NTROWS;
    for (int s = 0; s < NSTEPS; s++) {
        agg_kernel<<<aggBlocks, 256>>>(p_n, p_x);
        node_mlp_tc<<<nodeBlocks, NTROWS, nodeSmem>>>(
            p_x, s,
            pb0 + (size_t)s * HH,
            pb1 + (size_t)s * HH,
            pb2 + (size_t)s * LL,
            p_n);
    }

    // decoder + mask
    mlp3_kernel<64, 2><<<(NN + 31) / 32, 256>>>(
        p_n, dW0, db0, dW1, db1, dW2, db2, out, NN, nodes);
}

// round 13
// speedup vs baseline: 1.2036x; 1.2036x over previous
#include <cuda_runtime.h>
#include <cuda_bf16.h>
#include <cuda_fp16.h>
#include <math.h>

#define NN 50000
#define EE 1250000
#define HH 128
#define LL 64
#define NSTEPS 5
#define EPSV 1e-6f
#define SMSHIFT 30.0f

#define ETROWS 256
#define NTROWS 256

#define W0F_U (4 * 16 * 32 * 4)
#define W1F_U (8 * 16 * 32 * 4)
#define W2F_U (8 * 8 * 32 * 4)
#define WSTEP_U (W0F_U + W1F_U + W2F_U)

// ---------------- device scratch ----------------
__device__ __half2 g_elat[(size_t)EE * 32];   // edge latents fp16 (160 MB)
__device__ float g_n[NN * LL];
__device__ float g_x[NN * LL];
__device__ int   g_deg[NN];
__device__ int   g_rowstart[NN + 1];
__device__ int   g_cursor[NN];
__device__ int2  g_epair[EE];                 // CSR slot -> (edge id, sender)
__device__ unsigned g_wfrag[NSTEPS * WSTEP_U];

// ---------------- CSR build ----------------
__global__ void degree_kernel(const int* __restrict__ receivers) {
    int e = blockIdx.x * blockDim.x + threadIdx.x;
    if (e < EE) atomicAdd(&g_deg[receivers[e]], 1);
}
__global__ void scan_kernel() {
    __shared__ int ssum[1024];
    const int tid = threadIdx.x;
    const int chunk = (NN + 1023) / 1024;
    const int start = tid * chunk;
    const int cend = min(start + chunk, NN);
    int sum = 0;
    for (int i = start; i < cend; i++) sum += g_deg[i];
    ssum[tid] = sum;
    __syncthreads();
    if (tid == 0) {
        int run = 0;
        for (int i = 0; i < 1024; i++) { int v = ssum[i]; ssum[i] = run; run += v; }
        g_rowstart[NN] = run;
    }
    __syncthreads();
    int run = ssum[tid];
    for (int i = start; i < cend; i++) {
        g_rowstart[i] = run;
        g_cursor[i] = run;
        run += g_deg[i];
    }
}
__global__ void scatter_kernel(const int* __restrict__ receivers,
                               const int* __restrict__ senders) {
    int e = blockIdx.x * blockDim.x + threadIdx.x;
    if (e < EE) {
        int r = receivers[e];
        int p = atomicAdd(&g_cursor[r], 1);
        g_epair[p] = make_int2(e, senders[e]);
    }
}

// ---------------- bf16 split + mma helpers ----------------
__device__ __forceinline__ void split2(float a, float b, unsigned& hi, unsigned& lo) {
    __nv_bfloat16 ha = __float2bfloat16(a);
    __nv_bfloat16 hb = __float2bfloat16(b);
    float la = a - __bfloat162float(ha);
    float lb = b - __bfloat162float(hb);
    __nv_bfloat162 ph; ph.x = ha; ph.y = hb;
    __nv_bfloat162 pl = __floats2bfloat162_rn(la, lb);
    hi = *(unsigned*)&ph;
    lo = *(unsigned*)&pl;
}

__device__ __forceinline__ void mma_bf16(float* d, uint4 a, uint2 b) {
    asm volatile(
        "mma.sync.aligned.m16n8k16.row.col.f32.bf16.bf16.f32 "
        "{%0,%1,%2,%3}, {%4,%5,%6,%7}, {%8,%9}, {%0,%1,%2,%3};\n"
        : "+f"(d[0]), "+f"(d[1]), "+f"(d[2]), "+f"(d[3])
        : "r"(a.x), "r"(a.y), "r"(a.z), "r"(a.w), "r"(b.x), "r"(b.y));
}

__device__ __forceinline__ void mma3(float* d, uint4 ah, uint4 al, uint4 q) {
    uint2 bh = make_uint2(q.x, q.y);
    uint2 bl = make_uint2(q.z, q.w);
    mma_bf16(d, ah, bh);
    mma_bf16(d, ah, bl);
    mma_bf16(d, al, bh);
}

__device__ __forceinline__ void stage_bfrag_g(
    const float* __restrict__ W, int ncols, int KT, int NT, unsigned* dst,
    int tid, int nthreads)
{
    int total = KT * NT * 64;
    for (int idx = tid; idx < total; idx += nthreads) {
        int reg = idx & 1;
        int ln  = (idx >> 1) & 31;
        int fnt = (idx >> 6) % NT;
        int fkt = (idx >> 6) / NT;
        int k = fkt * 16 + reg * 8 + (ln & 3) * 2;
        int n = fnt * 8 + (ln >> 2);
        unsigned hi, lo;
        split2(__ldg(W + k * ncols + n), __ldg(W + (k + 1) * ncols + n), hi, lo);
        unsigned* cell = dst + ((size_t)(fkt * NT + fnt) * 32 + ln) * 4;
        cell[reg]     = hi;
        cell[2 + reg] = lo;
    }
}

// grid (NSTEPS, CHUNKS): parallel weight-fragment conversion
#define PREP_CHUNKS 8
__global__ void prep_wfrag_kernel(const float* __restrict__ pW0,
                                  const float* __restrict__ pW1,
                                  const float* __restrict__ pW2)
{
    int s = blockIdx.x;
    int tid = blockIdx.y * blockDim.x + threadIdx.x;
    int nth = PREP_CHUNKS * blockDim.x;
    unsigned* dst = g_wfrag + (size_t)s * WSTEP_U;
    stage_bfrag_g(pW0 + (size_t)s * LL * HH, HH, 4, 16, dst, tid, nth);
    stage_bfrag_g(pW1 + (size_t)s * HH * HH, HH, 8, 16, dst + W0F_U, tid, nth);
    stage_bfrag_g(pW2 + (size_t)s * HH * LL, LL, 8, 8,  dst + W0F_U + W1F_U, tid, nth);
}

// ---------------- tensor-core edge encoder: 3 -> 128 -> 128 -> 64 (fp16 out) ----------------
__global__ void __launch_bounds__(ETROWS, 1) edge_encoder_tc(
    const float* __restrict__ edges,
    const float* __restrict__ W0, const float* __restrict__ B0,
    const float* __restrict__ W1, const float* __restrict__ B1,
    const float* __restrict__ W2, const float* __restrict__ B2,
    __half2* __restrict__ Y)
{
    extern __shared__ unsigned smu[];
    unsigned* B1f = smu;
    unsigned* B2f = B1f + 8 * 16 * 32 * 4;

    const int tid  = threadIdx.x;
    const int lane = tid & 31;
    const int warp = tid >> 5;
    const int cbase = (lane & 3) * 2;

    stage_bfrag_g(W1, HH, 8, 16, B1f, tid, ETROWS);
    stage_bfrag_g(W2, LL, 8, 8,  B2f, tid, ETROWS);
    __syncthreads();

    float2 b1c[16], b2c[8];
#pragma unroll
    for (int nt = 0; nt < 16; nt++) b1c[nt] = __ldg((const float2*)(B1 + nt * 8 + cbase));
#pragma unroll
    for (int nt = 0; nt < 8;  nt++) b2c[nt] = __ldg((const float2*)(B2 + nt * 8 + cbase));

    const int ntiles = (EE + ETROWS - 1) / ETROWS;
    for (int tile = blockIdx.x; tile < ntiles; tile += gridDim.x) {
        const int row0 = tile * ETROWS;
        const int rb = row0 + warp * 32 + (lane >> 2);

        float xr[4][3];
#pragma unroll
        for (int j = 0; j < 4; j++) {
            int gr = rb + j * 8;
            bool ok = (gr < EE);
            const float* p = edges + (size_t)gr * 3;
            xr[j][0] = ok ? __ldg(p)     : 0.f;
            xr[j][1] = ok ? __ldg(p + 1) : 0.f;
            xr[j][2] = ok ? __ldg(p + 2) : 0.f;
        }

        float acc1[2][16][4];
#pragma unroll
        for (int nt = 0; nt < 16; nt++) {
#pragma unroll
            for (int mt = 0; mt < 2; mt++) {
                acc1[mt][nt][0] = b1c[nt].x; acc1[mt][nt][1] = b1c[nt].y;
                acc1[mt][nt][2] = b1c[nt].x; acc1[mt][nt][3] = b1c[nt].y;
            }
        }
#pragma unroll
        for (int kt = 0; kt < 8; kt++) {
            float v[4][4];
#pragma unroll
            for (int cc = 0; cc < 4; cc++) {
                int col = kt * 16 + cbase + (cc & 1) + ((cc >> 1) << 3);
                float w0v = __ldg(W0 + col);
                float w1v = __ldg(W0 + HH + col);
                float w2v = __ldg(W0 + 2 * HH + col);
                float bb  = __ldg(B0 + col);
#pragma unroll
                for (int j = 0; j < 4; j++) {
                    float t = fmaf(xr[j][2], w2v, fmaf(xr[j][1], w1v, fmaf(xr[j][0], w0v, bb)));
                    v[j][cc] = fmaxf(t, 0.f);
                }
            }
            uint4 AH[2], AL[2];
#pragma unroll
            for (int mt = 0; mt < 2; mt++) {
                split2(v[2 * mt][0],     v[2 * mt][1],     AH[mt].x, AL[mt].x);
                split2(v[2 * mt + 1][0], v[2 * mt + 1][1], AH[mt].y, AL[mt].y);
                split2(v[2 * mt][2],     v[2 * mt][3],     AH[mt].z, AL[mt].z);
                split2(v[2 * mt + 1][2], v[2 * mt + 1][3], AH[mt].w, AL[mt].w);
            }
#pragma unroll
            for (int nt = 0; nt < 16; nt++) {
                uint4 q = *(const uint4*)(B1f + ((size_t)(kt * 16 + nt) * 32 + lane) * 4);
                mma3(acc1[0][nt], AH[0], AL[0], q);
                mma3(acc1[1][nt], AH[1], AL[1], q);
            }
        }

        unsigned A2h[2][8][4], A2l[2][8][4];
#pragma unroll
        for (int mt = 0; mt < 2; mt++) {
#pragma unroll
            for (int nt = 0; nt < 16; nt++) {
                int kt2 = nt >> 1, half = (nt & 1) * 2;
                split2(fmaxf(acc1[mt][nt][0], 0.f), fmaxf(acc1[mt][nt][1], 0.f),
                       A2h[mt][kt2][half], A2l[mt][kt2][half]);
                split2(fmaxf(acc1[mt][nt][2], 0.f), fmaxf(acc1[mt][nt][3], 0.f),
                       A2h[mt][kt2][half + 1], A2l[mt][kt2][half + 1]);
            }
        }

        float acc2[2][8][4];
#pragma unroll
        for (int nt = 0; nt < 8; nt++) {
#pragma unroll
            for (int mt = 0; mt < 2; mt++) {
                acc2[mt][nt][0] = b2c[nt].x; acc2[mt][nt][1] = b2c[nt].y;
                acc2[mt][nt][2] = b2c[nt].x; acc2[mt][nt][3] = b2c[nt].y;
            }
        }
#pragma unroll
        for (int kt = 0; kt < 8; kt++) {
            uint4 a2h0 = make_uint4(A2h[0][kt][0], A2h[0][kt][1], A2h[0][kt][2], A2h[0][kt][3]);
            uint4 a2l0 = make_uint4(A2l[0][kt][0], A2l[0][kt][1], A2l[0][kt][2], A2l[0][kt][3]);
            uint4 a2h1 = make_uint4(A2h[1][kt][0], A2h[1][kt][1], A2h[1][kt][2], A2h[1][kt][3]);
            uint4 a2l1 = make_uint4(A2l[1][kt][0], A2l[1][kt][1], A2l[1][kt][2], A2l[1][kt][3]);
#pragma unroll
            for (int nt = 0; nt < 8; nt++) {
                uint4 q = *(const uint4*)(B2f + ((size_t)(kt * 8 + nt) * 32 + lane) * 4);
                mma3(acc2[0][nt], a2h0, a2l0, q);
                mma3(acc2[1][nt], a2h1, a2l1, q);
            }
        }

#pragma unroll
        for (int mt = 0; mt < 2; mt++) {
            int r0g = row0 + warp * 32 + mt * 16 + (lane >> 2);
            int r1g = r0g + 8;
#pragma unroll
            for (int nt = 0; nt < 8; nt++) {
                int cid = nt * 4 + (lane & 3);
                if (r0g < EE)
                    Y[(size_t)r0g * 32 + cid] = __floats2half2_rn(acc2[mt][nt][0], acc2[mt][nt][1]);
                if (r1g < EE)
                    Y[(size_t)r1g * 32 + cid] = __floats2half2_rn(acc2[mt][nt][2], acc2[mt][nt][3]);
            }
        }
    }
}

// ---------------- tensor-core node-step MLP: 64 -> 128 -> 128 -> 64 ----------------
__global__ void __launch_bounds__(NTROWS, 1) node_mlp_tc(
    const float* __restrict__ X,
    int step,
    const float* __restrict__ B0,
    const float* __restrict__ B1,
    const float* __restrict__ B2,
    float* __restrict__ Y)
{
    extern __shared__ unsigned smu[];
    unsigned* W0f = smu;
    unsigned* W1f = W0f + W0F_U;
    unsigned* W2f = W1f + W1F_U;

    {
        const uint4* src = (const uint4*)(g_wfrag + (size_t)step * WSTEP_U);
        uint4* dst = (uint4*)smu;
        for (int i = threadIdx.x; i < WSTEP_U / 4; i += NTROWS) dst[i] = __ldg(src + i);
    }
    __syncthreads();

    const int lane = threadIdx.x & 31;
    const int warp = threadIdx.x >> 5;
    const int cbase = (lane & 3) * 2;
    const int g0 = blockIdx.x * NTROWS + warp * 32 + (lane >> 2);

    float acc1[2][16][4];
#pragma unroll
    for (int nt = 0; nt < 16; nt++) {
        float2 b = __ldg((const float2*)(B0 + nt * 8 + cbase));
#pragma unroll
        for (int mt = 0; mt < 2; mt++) {
            acc1[mt][nt][0] = b.x; acc1[mt][nt][1] = b.y;
            acc1[mt][nt][2] = b.x; acc1[mt][nt][3] = b.y;
        }
    }
#pragma unroll
    for (int kt = 0; kt < 4; kt++) {
        uint4 AH[2], AL[2];
#pragma unroll
        for (int mt = 0; mt < 2; mt++) {
            int ga = g0 + mt * 16, gb = ga + 8;
            float2 z = make_float2(0.f, 0.f);
            float2 p0 = (ga < NN) ? *(const float2*)(X + (size_t)ga * LL + kt * 16 + cbase)     : z;
            float2 p1 = (gb < NN) ? *(const float2*)(X + (size_t)gb * LL + kt * 16 + cbase)     : z;
            float2 p2 = (ga < NN) ? *(const float2*)(X + (size_t)ga * LL + kt * 16 + cbase + 8) : z;
            float2 p3 = (gb < NN) ? *(const float2*)(X + (size_t)gb * LL + kt * 16 + cbase + 8) : z;
            split2(p0.x, p0.y, AH[mt].x, AL[mt].x);
            split2(p1.x, p1.y, AH[mt].y, AL[mt].y);
            split2(p2.x, p2.y, AH[mt].z, AL[mt].z);
            split2(p3.x, p3.y, AH[mt].w, AL[mt].w);
        }
#pragma unroll
        for (int nt = 0; nt < 16; nt++) {
            uint4 q = *(const uint4*)(W0f + ((size_t)(kt * 16 + nt) * 32 + lane) * 4);
            mma3(acc1[0][nt], AH[0], AL[0], q);
            mma3(acc1[1][nt], AH[1], AL[1], q);
        }
    }

    unsigned A2h[2][8][4], A2l[2][8][4];
#pragma unroll
    for (int mt = 0; mt < 2; mt++) {
        unsigned A1h[8][4], A1l[8][4];
#pragma unroll
        for (int nt = 0; nt < 16; nt++) {
            int kt2 = nt >> 1, half = (nt & 1) * 2;
            split2(fmaxf(acc1[mt][nt][0], 0.f), fmaxf(acc1[mt][nt][1], 0.f),
                   A1h[kt2][half], A1l[kt2][half]);
            split2(fmaxf(acc1[mt][nt][2], 0.f), fmaxf(acc1[mt][nt][3], 0.f),
                   A1h[kt2][half + 1], A1l[kt2][half + 1]);
        }
        float accB[16][4];
#pragma unroll
        for (int nt = 0; nt < 16; nt++) {
            float2 b = __ldg((const float2*)(B1 + nt * 8 + cbase));
            accB[nt][0] = b.x; accB[nt][1] = b.y; accB[nt][2] = b.x; accB[nt][3] = b.y;
        }
#pragma unroll
        for (int kt = 0; kt < 8; kt++) {
            uint4 ah = make_uint4(A1h[kt][0], A1h[kt][1], A1h[kt][2], A1h[kt][3]);
            uint4 al = make_uint4(A1l[kt][0], A1l[kt][1], A1l[kt][2], A1l[kt][3]);
#pragma unroll
            for (int nt = 0; nt < 16; nt++) {
                uint4 q = *(const uint4*)(W1f + ((size_t)(kt * 16 + nt) * 32 + lane) * 4);
                mma3(accB[nt], ah, al, q);
            }
        }
#pragma unroll
        for (int nt = 0; nt < 16; nt++) {
            int kt2 = nt >> 1, half = (nt & 1) * 2;
            split2(fmaxf(accB[nt][0], 0.f), fmaxf(accB[nt][1], 0.f),
                   A2h[mt][kt2][half], A2l[mt][kt2][half]);
            split2(fmaxf(accB[nt][2], 0.f), fmaxf(accB[nt][3], 0.f),
                   A2h[mt][kt2][half + 1], A2l[mt][kt2][half + 1]);
        }
    }

    float acc2[2][8][4];
#pragma unroll
    for (int nt = 0; nt < 8; nt++) {
        float2 b = __ldg((const float2*)(B2 + nt * 8 + cbase));
#pragma unroll
        for (int mt = 0; mt < 2; mt++) {
            acc2[mt][nt][0] = b.x; acc2[mt][nt][1] = b.y;
            acc2[mt][nt][2] = b.x; acc2[mt][nt][3] = b.y;
        }
    }
#pragma unroll
    for (int kt = 0; kt < 8; kt++) {
        uint4 a2h0 = make_uint4(A2h[0][kt][0], A2h[0][kt][1], A2h[0][kt][2], A2h[0][kt][3]);
        uint4 a2l0 = make_uint4(A2l[0][kt][0], A2l[0][kt][1], A2l[0][kt][2], A2l[0][kt][3]);
        uint4 a2h1 = make_uint4(A2h[1][kt][0], A2h[1][kt][1], A2h[1][kt][2], A2h[1][kt][3]);
        uint4 a2l1 = make_uint4(A2l[1][kt][0], A2l[1][kt][1], A2l[1][kt][2], A2l[1][kt][3]);
#pragma unroll
        for (int nt = 0; nt < 8; nt++) {
            uint4 q = *(const uint4*)(W2f + ((size_t)(kt * 8 + nt) * 32 + lane) * 4);
            mma3(acc2[0][nt], a2h0, a2l0, q);
            mma3(acc2[1][nt], a2h1, a2l1, q);
        }
    }

#pragma unroll
    for (int mt = 0; mt < 2; mt++) {
        int ga = g0 + mt * 16, gb = ga + 8;
#pragma unroll
        for (int nt = 0; nt < 8; nt++) {
            int colg = nt * 8 + cbase;
            if (ga < NN) {
                float2 o; o.x = acc2[mt][nt][0]; o.y = acc2[mt][nt][1];
                *(float2*)&Y[(size_t)ga * LL + colg] = o;
            }
            if (gb < NN) {
                float2 o; o.x = acc2[mt][nt][2]; o.y = acc2[mt][nt][3];
                *(float2*)&Y[(size_t)gb * LL + colg] = o;
            }
        }
    }
}

// ---------------- fused FFMA MLP (node encoder + decoder) ----------------
template <int IN, int OUT>
__global__ void __launch_bounds__(256) mlp3_kernel(
    const float* __restrict__ X,
    const float* __restrict__ W0, const float* __restrict__ B0,
    const float* __restrict__ W1, const float* __restrict__ B1,
    const float* __restrict__ W2, const float* __restrict__ B2,
    float* __restrict__ Y, int nrows,
    const float* __restrict__ mask_src)
{
    constexpr int RPW = 4;
    __shared__ float sh_h[8][HH * RPW];
    __shared__ float sh_x[8][IN * RPW];
    const int warp = threadIdx.x >> 5;
    const int lane = threadIdx.x & 31;
    const int row0 = (blockIdx.x * 8 + warp) * RPW;
    if (row0 >= nrows) return;
    float* hx = sh_x[warp];
    float* hh = sh_h[warp];

    for (int i = lane; i < IN; i += 32) {
#pragma unroll
        for (int r = 0; r < RPW; r++) {
            int row = row0 + r;
            hx[i * RPW + r] = (row < nrows) ? X[(size_t)row * IN + i] : 0.f;
        }
    }
    __syncwarp();

    const int j0 = lane << 2;
    float acc[RPW][4];
    {
        float4 b = *(const float4*)(B0 + j0);
#pragma unroll
        for (int r = 0; r < RPW; r++) { acc[r][0] = b.x; acc[r][1] = b.y; acc[r][2] = b.z; acc[r][3] = b.w; }
#pragma unroll
        for (int i = 0; i < IN; i++) {
            float4 w = __ldg((const float4*)(W0 + i * HH + j0));
#pragma unroll
            for (int r = 0; r < RPW; r++) {
                float xv = hx[i * RPW + r];
                acc[r][0] += xv * w.x; acc[r][1] += xv * w.y;
                acc[r][2] += xv * w.z; acc[r][3] += xv * w.w;
            }
        }
    }
#pragma unroll
    for (int jj = 0; jj < 4; jj++) {
        float4 v = make_float4(fmaxf(acc[0][jj], 0.f), fmaxf(acc[1][jj], 0.f),
                               fmaxf(acc[2][jj], 0.f), fmaxf(acc[3][jj], 0.f));
        *(float4*)(hh + (j0 + jj) * RPW) = v;
    }
    __syncwarp();
    {
        float4 b = *(const float4*)(B1 + j0);
#pragma unroll
        for (int r = 0; r < RPW; r++) { acc[r][0] = b.x; acc[r][1] = b.y; acc[r][2] = b.z; acc[r][3] = b.w; }
#pragma unroll 4
        for (int k = 0; k < HH; k++) {
            float4 w = __ldg((const float4*)(W1 + k * HH + j0));
            float4 hv = *(const float4*)(hh + k * RPW);
            acc[0][0] += hv.x * w.x; acc[0][1] += hv.x * w.y; acc[0][2] += hv.x * w.z; acc[0][3] += hv.x * w.w;
            acc[1][0] += hv.y * w.x; acc[1][1] += hv.y * w.y; acc[1][2] += hv.y * w.z; acc[1][3] += hv.y * w.w;
            acc[2][0] += hv.z * w.x; acc[2][1] += hv.z * w.y; acc[2][2] += hv.z * w.z; acc[2][3] += hv.z * w.w;
            acc[3][0] += hv.w * w.x; acc[3][1] += hv.w * w.y; acc[3][2] += hv.w * w.z; acc[3][3] += hv.w * w.w;
        }
    }
    __syncwarp();
#pragma unroll
    for (int jj = 0; jj < 4; jj++) {
        float4 v = make_float4(fmaxf(acc[0][jj], 0.f), fmaxf(acc[1][jj], 0.f),
                               fmaxf(acc[2][jj], 0.f), fmaxf(acc[3][jj], 0.f));
        *(float4*)(hh + (j0 + jj) * RPW) = v;
    }
    __syncwarp();

    constexpr int JV = (OUT >= 32) ? (OUT / 32) : 1;
    const int j2 = (OUT >= 32) ? lane * JV : lane;
    const bool act2 = (OUT >= 32) ? true : (lane < OUT);
    float a3[RPW][JV];
#pragma unroll
    for (int r = 0; r < RPW; r++)
#pragma unroll
        for (int jj = 0; jj < JV; jj++) a3[r][jj] = act2 ? B2[j2 + jj] : 0.f;

#pragma unroll 4
    for (int k = 0; k < HH; k++) {
        float4 hv = *(const float4*)(hh + k * RPW);
        if constexpr (JV == 2) {
            float2 w = __ldg((const float2*)(W2 + k * OUT + j2));
            a3[0][0] += hv.x * w.x; a3[0][1] += hv.x * w.y;
            a3[1][0] += hv.y * w.x; a3[1][1] += hv.y * w.y;
            a3[2][0] += hv.z * w.x; a3[2][1] += hv.z * w.y;
            a3[3][0] += hv.w * w.x; a3[3][1] += hv.w * w.y;
        } else {
            if (act2) {
                float w = __ldg(W2 + k * OUT + j2);
                a3[0][0] += hv.x * w; a3[1][0] += hv.y * w;
                a3[2][0] += hv.z * w; a3[3][0] += hv.w * w;
            }
        }
    }
#pragma unroll
    for (int r = 0; r < RPW; r++) {
        int row = row0 + r;
        if (row < nrows && act2) {
            float mk = 1.f;
            if (mask_src) {
                mk = ((fabsf(mask_src[row * 2]) + fabsf(mask_src[row * 2 + 1])) != 0.f) ? 1.f : 0.f;
            }
#pragma unroll
            for (int jj = 0; jj < JV; jj++)
                Y[(size_t)row * OUT + j2 + jj] = a3[r][jj] * mk;
        }
    }
}

// ---------------- softmax aggregation: fp16 elat, fp32 nin, simple 8-wide strip (R10 form) ----------------
__global__ void __launch_bounds__(256) agg_kernel(
    const float* __restrict__ nin,
    float* __restrict__ xout)
{
    const int gw = (blockIdx.x * blockDim.x + threadIdx.x) >> 5;
    if (gw >= NN) return;
    const int lane = threadIdx.x & 31;
    const int beg = __ldg(g_rowstart + gw);
    const int end = __ldg(g_rowstart + gw + 1);

    const float2* nin2 = (const float2*)nin;
    float S0 = 0.f, S1 = 0.f, A0 = 0.f, A1 = 0.f;

    int idx = beg;
    for (; idx + 8 <= end; idx += 8) {
        int2 pr[8];
#pragma unroll
        for (int u = 0; u < 8; u++) pr[u] = __ldg(g_epair + idx + u);
        float2 ev[8], nv[8];
#pragma unroll
        for (int u = 0; u < 8; u++)
            ev[u] = __half22float2(__ldg(g_elat + (size_t)pr[u].x * 32 + lane));
#pragma unroll
        for (int u = 0; u < 8; u++) nv[u] = __ldg(nin2 + (size_t)pr[u].y * 32 + lane);
#pragma unroll
        for (int u = 0; u < 8; u++) {
            float m0 = fmaxf(ev[u].x + nv[u].x, 0.f) + EPSV;
            float m1 = fmaxf(ev[u].y + nv[u].y, 0.f) + EPSV;
            float t0 = __expf(m0 - SMSHIFT);
            float t1 = __expf(m1 - SMSHIFT);
            S0 += t0; A0 = fmaf(t0, m0, A0);
            S1 += t1; A1 = fmaf(t1, m1, A1);
        }
    }
    for (; idx < end; idx++) {
        int2 pr = __ldg(g_epair + idx);
        float2 ea = __half22float2(__ldg(g_elat + (size_t)pr.x * 32 + lane));
        float2 na = __ldg(nin2 + (size_t)pr.y * 32 + lane);
        float m0 = fmaxf(ea.x + na.x, 0.f) + EPSV;
        float m1 = fmaxf(ea.y + na.y, 0.f) + EPSV;
        float t0 = __expf(m0 - SMSHIFT);
        float t1 = __expf(m1 - SMSHIFT);
        S0 += t0; A0 = fmaf(t0, m0, A0);
        S1 += t1; A1 = fmaf(t1, m1, A1);
    }

    float r0 = (S0 > 0.f) ? A0 / S0 : 0.f;
    float r1 = (S1 > 0.f) ? A1 / S1 : 0.f;
    float2 ns = __ldg(nin2 + (size_t)gw * 32 + lane);
    float2 o; o.x = ns.x + r0; o.y = ns.y + r1;
    *((float2*)xout + (size_t)gw * 32 + lane) = o;
}

// ---------------- launch ----------------
extern "C" void kernel_launch(void* const* d_in, const int* in_sizes, int n_in,
                              void* d_out, int out_size)
{
    const float* nodes     = (const float*)d_in[0];
    const float* edges     = (const float*)d_in[1];
    const int*   senders   = (const int*)  d_in[2];
    const int*   receivers = (const int*)  d_in[3];
    const float* enW0 = (const float*)d_in[4];  const float* enb0 = (const float*)d_in[5];
    const float* enW1 = (const float*)d_in[6];  const float* enb1 = (const float*)d_in[7];
    const float* enW2 = (const float*)d_in[8];  const float* enb2 = (const float*)d_in[9];
    const float* eeW0 = (const float*)d_in[10]; const float* eeb0 = (const float*)d_in[11];
    const float* eeW1 = (const float*)d_in[12]; const float* eeb1 = (const float*)d_in[13];
    const float* eeW2 = (const float*)d_in[14]; const float* eeb2 = (const float*)d_in[15];
    const float* pW0  = (const float*)d_in[16]; const float* pb0  = (const float*)d_in[17];
    const float* pW1  = (const float*)d_in[18]; const float* pb1  = (const float*)d_in[19];
    const float* pW2  = (const float*)d_in[20]; const float* pb2  = (const float*)d_in[21];
    const float* dW0  = (const float*)d_in[22]; const float* db0  = (const float*)d_in[23];
    const float* dW1  = (const float*)d_in[24]; const float* db1  = (const float*)d_in[25];
    const float* dW2  = (const float*)d_in[26]; const float* db2  = (const float*)d_in[27];
    float* out = (float*)d_out;

    __half2* p_elat = nullptr;
    float *p_n = nullptr, *p_x = nullptr;
    int* p_deg = nullptr;
    cudaGetSymbolAddress((void**)&p_elat, g_elat);
    cudaGetSymbolAddress((void**)&p_n,    g_n);
    cudaGetSymbolAddress((void**)&p_x,    g_x);
    cudaGetSymbolAddress((void**)&p_deg,  g_deg);

    // CSR build
    cudaMemsetAsync(p_deg, 0, NN * sizeof(int));
    degree_kernel<<<(EE + 255) / 256, 256>>>(receivers);
    scan_kernel<<<1, 1024>>>();
    scatter_kernel<<<(EE + 255) / 256, 256>>>(receivers, senders);

    // pre-convert step-MLP weights (parallel)
    {
        dim3 pgrid(NSTEPS, PREP_CHUNKS);
        prep_wfrag_kernel<<<pgrid, 256>>>(pW0, pW1, pW2);
    }

    // node encoder (FFMA)
    mlp3_kernel<2, 64><<<(NN + 31) / 32, 256>>>(
        nodes, enW0, enb0, enW1, enb1, enW2, enb2, p_n, NN, nullptr);

    // edge encoder (tensor cores, fp16 output)
    {
        const int smem = (8 * 16 * 32 * 4 + 8 * 8 * 32 * 4) * 4;
        cudaFuncSetAttribute(edge_encoder_tc,
                             cudaFuncAttributeMaxDynamicSharedMemorySize, smem);
        edge_encoder_tc<<<148, ETROWS, smem>>>(
            edges, eeW0, eeb0, eeW1, eeb1, eeW2, eeb2, p_elat);
    }

    // processor steps
    const int aggBlocks = (NN * 32 + 255) / 256;
    const int nodeSmem = WSTEP_U * 4;
    cudaFuncSetAttribute(node_mlp_tc,
                         cudaFuncAttributeMaxDynamicSharedMemorySize, nodeSmem);
    const int nodeBlocks = (NN + NTROWS - 1) / NTROWS;
    for (int s = 0; s < NSTEPS; s++) {
        agg_kernel<<<aggBlocks, 256>>>(p_n, p_x);
        node_mlp_tc<<<nodeBlocks, NTROWS, nodeSmem>>>(
            p_x, s,
            pb0 + (size_t)s * HH,
            pb1 + (size_t)s * HH,
            pb2 + (size_t)s * LL,
            p_n);
    }

    // decoder + mask
    mlp3_kernel<64, 2><<<(NN + 31) / 32, 256>>>(
        p_n, dW0, db0, dW1, db1, dW2, db2, out, NN, nodes);
}

// round 15
// speedup vs baseline: 1.2775x; 1.0613x over previous
#include <cuda_runtime.h>
#include <cuda_bf16.h>
#include <cuda_fp16.h>
#include <math.h>

#define NN 50000
#define EE 1250000
#define HH 128
#define LL 64
#define NSTEPS 5
#define EPSV 1e-6f
#define SMSHIFT 30.0f

#define ETROWS 256
#define NTROWS 256

#define W0F_U (4 * 16 * 32 * 4)
#define W1F_U (8 * 16 * 32 * 4)
#define W2F_U (8 * 8 * 32 * 4)
#define WSTEP_U (W0F_U + W1F_U + W2F_U)

// ---------------- device scratch ----------------
__device__ __half2 g_elat[(size_t)EE * 32];   // edge latents fp16 (160 MB)
__device__ float g_n[NN * LL];
__device__ float g_x[NN * LL];
__device__ int   g_deg[NN];
__device__ int   g_rowstart[NN + 1];
__device__ int   g_cursor[NN];
__device__ int2  g_epair[EE];                 // CSR slot -> (edge id, sender)
__device__ unsigned g_wfrag[NSTEPS * WSTEP_U];

// ---------------- CSR build ----------------
__global__ void degree_kernel(const int* __restrict__ receivers) {
    int e = blockIdx.x * blockDim.x + threadIdx.x;
    if (e < EE) atomicAdd(&g_deg[receivers[e]], 1);
}
__global__ void scan_kernel() {
    __shared__ int ssum[1024];
    const int tid = threadIdx.x;
    const int chunk = (NN + 1023) / 1024;
    const int start = tid * chunk;
    const int cend = min(start + chunk, NN);
    int sum = 0;
    for (int i = start; i < cend; i++) sum += g_deg[i];
    ssum[tid] = sum;
    __syncthreads();
    if (tid == 0) {
        int run = 0;
        for (int i = 0; i < 1024; i++) { int v = ssum[i]; ssum[i] = run; run += v; }
        g_rowstart[NN] = run;
    }
    __syncthreads();
    int run = ssum[tid];
    for (int i = start; i < cend; i++) {
        g_rowstart[i] = run;
        g_cursor[i] = run;
        run += g_deg[i];
    }
}
__global__ void scatter_kernel(const int* __restrict__ receivers,
                               const int* __restrict__ senders) {
    int e = blockIdx.x * blockDim.x + threadIdx.x;
    if (e < EE) {
        int r = receivers[e];
        int p = atomicAdd(&g_cursor[r], 1);
        g_epair[p] = make_int2(e, senders[e]);
    }
}

// ---------------- bf16 split + mma helpers ----------------
__device__ __forceinline__ void split2(float a, float b, unsigned& hi, unsigned& lo) {
    __nv_bfloat16 ha = __float2bfloat16(a);
    __nv_bfloat16 hb = __float2bfloat16(b);
    float la = a - __bfloat162float(ha);
    float lb = b - __bfloat162float(hb);
    __nv_bfloat162 ph; ph.x = ha; ph.y = hb;
    __nv_bfloat162 pl = __floats2bfloat162_rn(la, lb);
    hi = *(unsigned*)&ph;
    lo = *(unsigned*)&pl;
}

__device__ __forceinline__ void mma_bf16(float* d, uint4 a, uint2 b) {
    asm volatile(
        "mma.sync.aligned.m16n8k16.row.col.f32.bf16.bf16.f32 "
        "{%0,%1,%2,%3}, {%4,%5,%6,%7}, {%8,%9}, {%0,%1,%2,%3};\n"
        : "+f"(d[0]), "+f"(d[1]), "+f"(d[2]), "+f"(d[3])
        : "r"(a.x), "r"(a.y), "r"(a.z), "r"(a.w), "r"(b.x), "r"(b.y));
}

__device__ __forceinline__ void mma3(float* d, uint4 ah, uint4 al, uint4 q) {
    uint2 bh = make_uint2(q.x, q.y);
    uint2 bl = make_uint2(q.z, q.w);
    mma_bf16(d, ah, bh);
    mma_bf16(d, ah, bl);
    mma_bf16(d, al, bh);
}

__device__ __forceinline__ void stage_bfrag_g(
    const float* __restrict__ W, int ncols, int KT, int NT, unsigned* dst,
    int tid, int nthreads)
{
    int total = KT * NT * 64;
    for (int idx = tid; idx < total; idx += nthreads) {
        int reg = idx & 1;
        int ln  = (idx >> 1) & 31;
        int fnt = (idx >> 6) % NT;
        int fkt = (idx >> 6) / NT;
        int k = fkt * 16 + reg * 8 + (ln & 3) * 2;
        int n = fnt * 8 + (ln >> 2);
        unsigned hi, lo;
        split2(__ldg(W + k * ncols + n), __ldg(W + (k + 1) * ncols + n), hi, lo);
        unsigned* cell = dst + ((size_t)(fkt * NT + fnt) * 32 + ln) * 4;
        cell[reg]     = hi;
        cell[2 + reg] = lo;
    }
}

// grid (NSTEPS, CHUNKS): parallel weight-fragment conversion
#define PREP_CHUNKS 8
__global__ void prep_wfrag_kernel(const float* __restrict__ pW0,
                                  const float* __restrict__ pW1,
                                  const float* __restrict__ pW2)
{
    int s = blockIdx.x;
    int tid = blockIdx.y * blockDim.x + threadIdx.x;
    int nth = PREP_CHUNKS * blockDim.x;
    unsigned* dst = g_wfrag + (size_t)s * WSTEP_U;
    stage_bfrag_g(pW0 + (size_t)s * LL * HH, HH, 4, 16, dst, tid, nth);
    stage_bfrag_g(pW1 + (size_t)s * HH * HH, HH, 8, 16, dst + W0F_U, tid, nth);
    stage_bfrag_g(pW2 + (size_t)s * HH * LL, LL, 8, 8,  dst + W0F_U + W1F_U, tid, nth);
}

// ---------------- tensor-core 3-layer encoder: IN -> 128 -> 128 -> 64 ----------------
// HALFOUT=true : write fp16 half2 in elat layout (32 half2/row, pair id nt*4+lane%4)
// HALFOUT=false: write fp32 rows of LL floats
template <int IN, bool HALFOUT>
__global__ void __launch_bounds__(ETROWS, 1) enc3_tc(
    const float* __restrict__ Xin,
    const float* __restrict__ W0, const float* __restrict__ B0,
    const float* __restrict__ W1, const float* __restrict__ B1,
    const float* __restrict__ W2, const float* __restrict__ B2,
    void* __restrict__ Yout, int nrows)
{
    extern __shared__ unsigned smu[];
    unsigned* B1f = smu;
    unsigned* B2f = B1f + 8 * 16 * 32 * 4;

    const int tid  = threadIdx.x;
    const int lane = tid & 31;
    const int warp = tid >> 5;
    const int cbase = (lane & 3) * 2;

    stage_bfrag_g(W1, HH, 8, 16, B1f, tid, ETROWS);
    stage_bfrag_g(W2, LL, 8, 8,  B2f, tid, ETROWS);
    __syncthreads();

    float2 b1c[16], b2c[8];
#pragma unroll
    for (int nt = 0; nt < 16; nt++) b1c[nt] = __ldg((const float2*)(B1 + nt * 8 + cbase));
#pragma unroll
    for (int nt = 0; nt < 8;  nt++) b2c[nt] = __ldg((const float2*)(B2 + nt * 8 + cbase));

    const int ntiles = (nrows + ETROWS - 1) / ETROWS;
    for (int tile = blockIdx.x; tile < ntiles; tile += gridDim.x) {
        const int row0 = tile * ETROWS;
        const int rb = row0 + warp * 32 + (lane >> 2);

        float xr[4][IN];
#pragma unroll
        for (int j = 0; j < 4; j++) {
            int gr = rb + j * 8;
            bool ok = (gr < nrows);
            const float* p = Xin + (size_t)gr * IN;
#pragma unroll
            for (int c = 0; c < IN; c++) xr[j][c] = ok ? __ldg(p + c) : 0.f;
        }

        // layer 0 (FFMA) fused into layer 1 (MMA) over kt
        float acc1[2][16][4];
#pragma unroll
        for (int nt = 0; nt < 16; nt++) {
#pragma unroll
            for (int mt = 0; mt < 2; mt++) {
                acc1[mt][nt][0] = b1c[nt].x; acc1[mt][nt][1] = b1c[nt].y;
                acc1[mt][nt][2] = b1c[nt].x; acc1[mt][nt][3] = b1c[nt].y;
            }
        }
#pragma unroll
        for (int kt = 0; kt < 8; kt++) {
            float v[4][4];
#pragma unroll
            for (int cc = 0; cc < 4; cc++) {
                int col = kt * 16 + cbase + (cc & 1) + ((cc >> 1) << 3);
                float wv[IN];
#pragma unroll
                for (int c = 0; c < IN; c++) wv[c] = __ldg(W0 + c * HH + col);
                float bb = __ldg(B0 + col);
#pragma unroll
                for (int j = 0; j < 4; j++) {
                    float t = bb;
#pragma unroll
                    for (int c = 0; c < IN; c++) t = fmaf(xr[j][c], wv[c], t);
                    v[j][cc] = fmaxf(t, 0.f);
                }
            }
            uint4 AH[2], AL[2];
#pragma unroll
            for (int mt = 0; mt < 2; mt++) {
                split2(v[2 * mt][0],     v[2 * mt][1],     AH[mt].x, AL[mt].x);
                split2(v[2 * mt + 1][0], v[2 * mt + 1][1], AH[mt].y, AL[mt].y);
                split2(v[2 * mt][2],     v[2 * mt][3],     AH[mt].z, AL[mt].z);
                split2(v[2 * mt + 1][2], v[2 * mt + 1][3], AH[mt].w, AL[mt].w);
            }
#pragma unroll
            for (int nt = 0; nt < 16; nt++) {
                uint4 q = *(const uint4*)(B1f + ((size_t)(kt * 16 + nt) * 32 + lane) * 4);
                mma3(acc1[0][nt], AH[0], AL[0], q);
                mma3(acc1[1][nt], AH[1], AL[1], q);
            }
        }

        // relu + register permute: C-frag -> A-frag
        unsigned A2h[2][8][4], A2l[2][8][4];
#pragma unroll
        for (int mt = 0; mt < 2; mt++) {
#pragma unroll
            for (int nt = 0; nt < 16; nt++) {
                int kt2 = nt >> 1, half = (nt & 1) * 2;
                split2(fmaxf(acc1[mt][nt][0], 0.f), fmaxf(acc1[mt][nt][1], 0.f),
                       A2h[mt][kt2][half], A2l[mt][kt2][half]);
                split2(fmaxf(acc1[mt][nt][2], 0.f), fmaxf(acc1[mt][nt][3], 0.f),
                       A2h[mt][kt2][half + 1], A2l[mt][kt2][half + 1]);
            }
        }

        // layer 2: K=128 -> N=64
        float acc2[2][8][4];
#pragma unroll
        for (int nt = 0; nt < 8; nt++) {
#pragma unroll
            for (int mt = 0; mt < 2; mt++) {
                acc2[mt][nt][0] = b2c[nt].x; acc2[mt][nt][1] = b2c[nt].y;
                acc2[mt][nt][2] = b2c[nt].x; acc2[mt][nt][3] = b2c[nt].y;
            }
        }
#pragma unroll
        for (int kt = 0; kt < 8; kt++) {
            uint4 a2h0 = make_uint4(A2h[0][kt][0], A2h[0][kt][1], A2h[0][kt][2], A2h[0][kt][3]);
            uint4 a2l0 = make_uint4(A2l[0][kt][0], A2l[0][kt][1], A2l[0][kt][2], A2l[0][kt][3]);
            uint4 a2h1 = make_uint4(A2h[1][kt][0], A2h[1][kt][1], A2h[1][kt][2], A2h[1][kt][3]);
            uint4 a2l1 = make_uint4(A2l[1][kt][0], A2l[1][kt][1], A2l[1][kt][2], A2l[1][kt][3]);
#pragma unroll
            for (int nt = 0; nt < 8; nt++) {
                uint4 q = *(const uint4*)(B2f + ((size_t)(kt * 8 + nt) * 32 + lane) * 4);
                mma3(acc2[0][nt], a2h0, a2l0, q);
                mma3(acc2[1][nt], a2h1, a2l1, q);
            }
        }

        // store
#pragma unroll
        for (int mt = 0; mt < 2; mt++) {
            int r0g = row0 + warp * 32 + mt * 16 + (lane >> 2);
            int r1g = r0g + 8;
#pragma unroll
            for (int nt = 0; nt < 8; nt++) {
                if (HALFOUT) {
                    __half2* Y = (__half2*)Yout;
                    int cid = nt * 4 + (lane & 3);
                    if (r0g < nrows)
                        Y[(size_t)r0g * 32 + cid] = __floats2half2_rn(acc2[mt][nt][0], acc2[mt][nt][1]);
                    if (r1g < nrows)
                        Y[(size_t)r1g * 32 + cid] = __floats2half2_rn(acc2[mt][nt][2], acc2[mt][nt][3]);
                } else {
                    float* Y = (float*)Yout;
                    int colg = nt * 8 + cbase;
                    if (r0g < nrows) {
                        float2 o; o.x = acc2[mt][nt][0]; o.y = acc2[mt][nt][1];
                        *(float2*)&Y[(size_t)r0g * LL + colg] = o;
                    }
                    if (r1g < nrows) {
                        float2 o; o.x = acc2[mt][nt][2]; o.y = acc2[mt][nt][3];
                        *(float2*)&Y[(size_t)r1g * LL + colg] = o;
                    }
                }
            }
        }
    }
}

// ---------------- tensor-core node-step MLP: 64 -> 128 -> 128 -> 64 ----------------
__global__ void __launch_bounds__(NTROWS, 1) node_mlp_tc(
    const float* __restrict__ X,
    int step,
    const float* __restrict__ B0,
    const float* __restrict__ B1,
    const float* __restrict__ B2,
    float* __restrict__ Y)
{
    extern __shared__ unsigned smu[];
    unsigned* W0f = smu;
    unsigned* W1f = W0f + W0F_U;
    unsigned* W2f = W1f + W1F_U;

    {
        const uint4* src = (const uint4*)(g_wfrag + (size_t)step * WSTEP_U);
        uint4* dst = (uint4*)smu;
        for (int i = threadIdx.x; i < WSTEP_U / 4; i += NTROWS) dst[i] = __ldg(src + i);
    }
    __syncthreads();

    const int lane = threadIdx.x & 31;
    const int warp = threadIdx.x >> 5;
    const int cbase = (lane & 3) * 2;
    const int g0 = blockIdx.x * NTROWS + warp * 32 + (lane >> 2);

    float acc1[2][16][4];
#pragma unroll
    for (int nt = 0; nt < 16; nt++) {
        float2 b = __ldg((const float2*)(B0 + nt * 8 + cbase));
#pragma unroll
        for (int mt = 0; mt < 2; mt++) {
            acc1[mt][nt][0] = b.x; acc1[mt][nt][1] = b.y;
            acc1[mt][nt][2] = b.x; acc1[mt][nt][3] = b.y;
        }
    }
#pragma unroll
    for (int kt = 0; kt < 4; kt++) {
        uint4 AH[2], AL[2];
#pragma unroll
        for (int mt = 0; mt < 2; mt++) {
            int ga = g0 + mt * 16, gb = ga + 8;
            float2 z = make_float2(0.f, 0.f);
            float2 p0 = (ga < NN) ? *(const float2*)(X + (size_t)ga * LL + kt * 16 + cbase)     : z;
            float2 p1 = (gb < NN) ? *(const float2*)(X + (size_t)gb * LL + kt * 16 + cbase)     : z;
            float2 p2 = (ga < NN) ? *(const float2*)(X + (size_t)ga * LL + kt * 16 + cbase + 8) : z;
            float2 p3 = (gb < NN) ? *(const float2*)(X + (size_t)gb * LL + kt * 16 + cbase + 8) : z;
            split2(p0.x, p0.y, AH[mt].x, AL[mt].x);
            split2(p1.x, p1.y, AH[mt].y, AL[mt].y);
            split2(p2.x, p2.y, AH[mt].z, AL[mt].z);
            split2(p3.x, p3.y, AH[mt].w, AL[mt].w);
        }
#pragma unroll
        for (int nt = 0; nt < 16; nt++) {
            uint4 q = *(const uint4*)(W0f + ((size_t)(kt * 16 + nt) * 32 + lane) * 4);
            mma3(acc1[0][nt], AH[0], AL[0], q);
            mma3(acc1[1][nt], AH[1], AL[1], q);
        }
    }

    unsigned A2h[2][8][4], A2l[2][8][4];
#pragma unroll
    for (int mt = 0; mt < 2; mt++) {
        unsigned A1h[8][4], A1l[8][4];
#pragma unroll
        for (int nt = 0; nt < 16; nt++) {
            int kt2 = nt >> 1, half = (nt & 1) * 2;
            split2(fmaxf(acc1[mt][nt][0], 0.f), fmaxf(acc1[mt][nt][1], 0.f),
                   A1h[kt2][half], A1l[kt2][half]);
            split2(fmaxf(acc1[mt][nt][2], 0.f), fmaxf(acc1[mt][nt][3], 0.f),
                   A1h[kt2][half + 1], A1l[kt2][half + 1]);
        }
        float accB[16][4];
#pragma unroll
        for (int nt = 0; nt < 16; nt++) {
            float2 b = __ldg((const float2*)(B1 + nt * 8 + cbase));
            accB[nt][0] = b.x; accB[nt][1] = b.y; accB[nt][2] = b.x; accB[nt][3] = b.y;
        }
#pragma unroll
        for (int kt = 0; kt < 8; kt++) {
            uint4 ah = make_uint4(A1h[kt][0], A1h[kt][1], A1h[kt][2], A1h[kt][3]);
            uint4 al = make_uint4(A1l[kt][0], A1l[kt][1], A1l[kt][2], A1l[kt][3]);
#pragma unroll
            for (int nt = 0; nt < 16; nt++) {
                uint4 q = *(const uint4*)(W1f + ((size_t)(kt * 16 + nt) * 32 + lane) * 4);
                mma3(accB[nt], ah, al, q);
            }
        }
#pragma unroll
        for (int nt = 0; nt < 16; nt++) {
            int kt2 = nt >> 1, half = (nt & 1) * 2;
            split2(fmaxf(accB[nt][0], 0.f), fmaxf(accB[nt][1], 0.f),
                   A2h[mt][kt2][half], A2l[mt][kt2][half]);
            split2(fmaxf(accB[nt][2], 0.f), fmaxf(accB[nt][3], 0.f),
                   A2h[mt][kt2][half + 1], A2l[mt][kt2][half + 1]);
        }
    }

    float acc2[2][8][4];
#pragma unroll
    for (int nt = 0; nt < 8; nt++) {
        float2 b = __ldg((const float2*)(B2 + nt * 8 + cbase));
#pragma unroll
        for (int mt = 0; mt < 2; mt++) {
            acc2[mt][nt][0] = b.x; acc2[mt][nt][1] = b.y;
            acc2[mt][nt][2] = b.x; acc2[mt][nt][3] = b.y;
        }
    }
#pragma unroll
    for (int kt = 0; kt < 8; kt++) {
        uint4 a2h0 = make_uint4(A2h[0][kt][0], A2h[0][kt][1], A2h[0][kt][2], A2h[0][kt][3]);
        uint4 a2l0 = make_uint4(A2l[0][kt][0], A2l[0][kt][1], A2l[0][kt][2], A2l[0][kt][3]);
        uint4 a2h1 = make_uint4(A2h[1][kt][0], A2h[1][kt][1], A2h[1][kt][2], A2h[1][kt][3]);
        uint4 a2l1 = make_uint4(A2l[1][kt][0], A2l[1][kt][1], A2l[1][kt][2], A2l[1][kt][3]);
#pragma unroll
        for (int nt = 0; nt < 8; nt++) {
            uint4 q = *(const uint4*)(W2f + ((size_t)(kt * 8 + nt) * 32 + lane) * 4);
            mma3(acc2[0][nt], a2h0, a2l0, q);
            mma3(acc2[1][nt], a2h1, a2l1, q);
        }
    }

#pragma unroll
    for (int mt = 0; mt < 2; mt++) {
        int ga = g0 + mt * 16, gb = ga + 8;
#pragma unroll
        for (int nt = 0; nt < 8; nt++) {
            int colg = nt * 8 + cbase;
            if (ga < NN) {
                float2 o; o.x = acc2[mt][nt][0]; o.y = acc2[mt][nt][1];
                *(float2*)&Y[(size_t)ga * LL + colg] = o;
            }
            if (gb < NN) {
                float2 o; o.x = acc2[mt][nt][2]; o.y = acc2[mt][nt][3];
                *(float2*)&Y[(size_t)gb * LL + colg] = o;
            }
        }
    }
}

// ---------------- fused FFMA MLP (decoder only) ----------------
template <int IN, int OUT>
__global__ void __launch_bounds__(256) mlp3_kernel(
    const float* __restrict__ X,
    const float* __restrict__ W0, const float* __restrict__ B0,
    const float* __restrict__ W1, const float* __restrict__ B1,
    const float* __restrict__ W2, const float* __restrict__ B2,
    float* __restrict__ Y, int nrows,
    const float* __restrict__ mask_src)
{
    constexpr int RPW = 4;
    __shared__ float sh_h[8][HH * RPW];
    __shared__ float sh_x[8][IN * RPW];
    const int warp = threadIdx.x >> 5;
    const int lane = threadIdx.x & 31;
    const int row0 = (blockIdx.x * 8 + warp) * RPW;
    if (row0 >= nrows) return;
    float* hx = sh_x[warp];
    float* hh = sh_h[warp];

    for (int i = lane; i < IN; i += 32) {
#pragma unroll
        for (int r = 0; r < RPW; r++) {
            int row = row0 + r;
            hx[i * RPW + r] = (row < nrows) ? X[(size_t)row * IN + i] : 0.f;
        }
    }
    __syncwarp();

    const int j0 = lane << 2;
    float acc[RPW][4];
    {
        float4 b = *(const float4*)(B0 + j0);
#pragma unroll
        for (int r = 0; r < RPW; r++) { acc[r][0] = b.x; acc[r][1] = b.y; acc[r][2] = b.z; acc[r][3] = b.w; }
#pragma unroll
        for (int i = 0; i < IN; i++) {
            float4 w = __ldg((const float4*)(W0 + i * HH + j0));
#pragma unroll
            for (int r = 0; r < RPW; r++) {
                float xv = hx[i * RPW + r];
                acc[r][0] += xv * w.x; acc[r][1] += xv * w.y;
                acc[r][2] += xv * w.z; acc[r][3] += xv * w.w;
            }
        }
    }
#pragma unroll
    for (int jj = 0; jj < 4; jj++) {
        float4 v = make_float4(fmaxf(acc[0][jj], 0.f), fmaxf(acc[1][jj], 0.f),
                               fmaxf(acc[2][jj], 0.f), fmaxf(acc[3][jj], 0.f));
        *(float4*)(hh + (j0 + jj) * RPW) = v;
    }
    __syncwarp();
    {
        float4 b = *(const float4*)(B1 + j0);
#pragma unroll
        for (int r = 0; r < RPW; r++) { acc[r][0] = b.x; acc[r][1] = b.y; acc[r][2] = b.z; acc[r][3] = b.w; }
#pragma unroll 4
        for (int k = 0; k < HH; k++) {
            float4 w = __ldg((const float4*)(W1 + k * HH + j0));
            float4 hv = *(const float4*)(hh + k * RPW);
            acc[0][0] += hv.x * w.x; acc[0][1] += hv.x * w.y; acc[0][2] += hv.x * w.z; acc[0][3] += hv.x * w.w;
            acc[1][0] += hv.y * w.x; acc[1][1] += hv.y * w.y; acc[1][2] += hv.y * w.z; acc[1][3] += hv.y * w.w;
            acc[2][0] += hv.z * w.x; acc[2][1] += hv.z * w.y; acc[2][2] += hv.z * w.z; acc[2][3] += hv.z * w.w;
            acc[3][0] += hv.w * w.x; acc[3][1] += hv.w * w.y; acc[3][2] += hv.w * w.z; acc[3][3] += hv.w * w.w;
        }
    }
    __syncwarp();
#pragma unroll
    for (int jj = 0; jj < 4; jj++) {
        float4 v = make_float4(fmaxf(acc[0][jj], 0.f), fmaxf(acc[1][jj], 0.f),
                               fmaxf(acc[2][jj], 0.f), fmaxf(acc[3][jj], 0.f));
        *(float4*)(hh + (j0 + jj) * RPW) = v;
    }
    __syncwarp();

    constexpr int JV = (OUT >= 32) ? (OUT / 32) : 1;
    const int j2 = (OUT >= 32) ? lane * JV : lane;
    const bool act2 = (OUT >= 32) ? true : (lane < OUT);
    float a3[RPW][JV];
#pragma unroll
    for (int r = 0; r < RPW; r++)
#pragma unroll
        for (int jj = 0; jj < JV; jj++) a3[r][jj] = act2 ? B2[j2 + jj] : 0.f;

#pragma unroll 4
    for (int k = 0; k < HH; k++) {
        float4 hv = *(const float4*)(hh + k * RPW);
        if constexpr (JV == 2) {
            float2 w = __ldg((const float2*)(W2 + k * OUT + j2));
            a3[0][0] += hv.x * w.x; a3[0][1] += hv.x * w.y;
            a3[1][0] += hv.y * w.x; a3[1][1] += hv.y * w.y;
            a3[2][0] += hv.z * w.x; a3[2][1] += hv.z * w.y;
            a3[3][0] += hv.w * w.x; a3[3][1] += hv.w * w.y;
        } else {
            if (act2) {
                float w = __ldg(W2 + k * OUT + j2);
                a3[0][0] += hv.x * w; a3[1][0] += hv.y * w;
                a3[2][0] += hv.z * w; a3[3][0] += hv.w * w;
            }
        }
    }
#pragma unroll
    for (int r = 0; r < RPW; r++) {
        int row = row0 + r;
        if (row < nrows && act2) {
            float mk = 1.f;
            if (mask_src) {
                mk = ((fabsf(mask_src[row * 2]) + fabsf(mask_src[row * 2 + 1])) != 0.f) ? 1.f : 0.f;
            }
#pragma unroll
            for (int jj = 0; jj < JV; jj++)
                Y[(size_t)row * OUT + j2 + jj] = a3[r][jj] * mk;
        }
    }
}

// ---------------- softmax aggregation: fp16 elat, fp32 nin, simple 8-wide strip ----------------
__global__ void __launch_bounds__(256) agg_kernel(
    const float* __restrict__ nin,
    float* __restrict__ xout)
{
    const int gw = (blockIdx.x * blockDim.x + threadIdx.x) >> 5;
    if (gw >= NN) return;
    const int lane = threadIdx.x & 31;
    const int beg = __ldg(g_rowstart + gw);
    const int end = __ldg(g_rowstart + gw + 1);

    const float2* nin2 = (const float2*)nin;
    float S0 = 0.f, S1 = 0.f, A0 = 0.f, A1 = 0.f;

    int idx = beg;
    for (; idx + 8 <= end; idx += 8) {
        int2 pr[8];
#pragma unroll
        for (int u = 0; u < 8; u++) pr[u] = __ldg(g_epair + idx + u);
        float2 ev[8], nv[8];
#pragma unroll
        for (int u = 0; u < 8; u++)
            ev[u] = __half22float2(__ldg(g_elat + (size_t)pr[u].x * 32 + lane));
#pragma unroll
        for (int u = 0; u < 8; u++) nv[u] = __ldg(nin2 + (size_t)pr[u].y * 32 + lane);
#pragma unroll
        for (int u = 0; u < 8; u++) {
            float m0 = fmaxf(ev[u].x + nv[u].x, 0.f) + EPSV;
            float m1 = fmaxf(ev[u].y + nv[u].y, 0.f) + EPSV;
            float t0 = __expf(m0 - SMSHIFT);
            float t1 = __expf(m1 - SMSHIFT);
            S0 += t0; A0 = fmaf(t0, m0, A0);
            S1 += t1; A1 = fmaf(t1, m1, A1);
        }
    }
    for (; idx < end; idx++) {
        int2 pr = __ldg(g_epair + idx);
        float2 ea = __half22float2(__ldg(g_elat + (size_t)pr.x * 32 + lane));
        float2 na = __ldg(nin2 + (size_t)pr.y * 32 + lane);
        float m0 = fmaxf(ea.x + na.x, 0.f) + EPSV;
        float m1 = fmaxf(ea.y + na.y, 0.f) + EPSV;
        float t0 = __expf(m0 - SMSHIFT);
        float t1 = __expf(m1 - SMSHIFT);
        S0 += t0; A0 = fmaf(t0, m0, A0);
        S1 += t1; A1 = fmaf(t1, m1, A1);
    }

    float r0 = (S0 > 0.f) ? A0 / S0 : 0.f;
    float r1 = (S1 > 0.f) ? A1 / S1 : 0.f;
    float2 ns = __ldg(nin2 + (size_t)gw * 32 + lane);
    float2 o; o.x = ns.x + r0; o.y = ns.y + r1;
    *((float2*)xout + (size_t)gw * 32 + lane) = o;
}

// ---------------- launch ----------------
extern "C" void kernel_launch(void* const* d_in, const int* in_sizes, int n_in,
                              void* d_out, int out_size)
{
    const float* nodes     = (const float*)d_in[0];
    const float* edges     = (const float*)d_in[1];
    const int*   senders   = (const int*)  d_in[2];
    const int*   receivers = (const int*)  d_in[3];
    const float* enW0 = (const float*)d_in[4];  const float* enb0 = (const float*)d_in[5];
    const float* enW1 = (const float*)d_in[6];  const float* enb1 = (const float*)d_in[7];
    const float* enW2 = (const float*)d_in[8];  const float* enb2 = (const float*)d_in[9];
    const float* eeW0 = (const float*)d_in[10]; const float* eeb0 = (const float*)d_in[11];
    const float* eeW1 = (const float*)d_in[12]; const float* eeb1 = (const float*)d_in[13];
    const float* eeW2 = (const float*)d_in[14]; const float* eeb2 = (const float*)d_in[15];
    const float* pW0  = (const float*)d_in[16]; const float* pb0  = (const float*)d_in[17];
    const float* pW1  = (const float*)d_in[18]; const float* pb1  = (const float*)d_in[19];
    const float* pW2  = (const float*)d_in[20]; const float* pb2  = (const float*)d_in[21];
    const float* dW0  = (const float*)d_in[22]; const float* db0  = (const float*)d_in[23];
    const float* dW1  = (const float*)d_in[24]; const float* db1  = (const float*)d_in[25];
    const float* dW2  = (const float*)d_in[26]; const float* db2  = (const float*)d_in[27];
    float* out = (float*)d_out;

    __half2* p_elat = nullptr;
    float *p_n = nullptr, *p_x = nullptr;
    int* p_deg = nullptr;
    cudaGetSymbolAddress((void**)&p_elat, g_elat);
    cudaGetSymbolAddress((void**)&p_n,    g_n);
    cudaGetSymbolAddress((void**)&p_x,    g_x);
    cudaGetSymbolAddress((void**)&p_deg,  g_deg);

    // CSR build
    cudaMemsetAsync(p_deg, 0, NN * sizeof(int));
    degree_kernel<<<(EE + 255) / 256, 256>>>(receivers);
    scan_kernel<<<1, 1024>>>();
    scatter_kernel<<<(EE + 255) / 256, 256>>>(receivers, senders);

    // pre-convert step-MLP weights (parallel)
    {
        dim3 pgrid(NSTEPS, PREP_CHUNKS);
        prep_wfrag_kernel<<<pgrid, 256>>>(pW0, pW1, pW2);
    }

    const int encSmem = (8 * 16 * 32 * 4 + 8 * 8 * 32 * 4) * 4;
    cudaFuncSetAttribute(enc3_tc<2, false>,
                         cudaFuncAttributeMaxDynamicSharedMemorySize, encSmem);
    cudaFuncSetAttribute(enc3_tc<3, true>,
                         cudaFuncAttributeMaxDynamicSharedMemorySize, encSmem);

    // node encoder (tensor cores, fp32 out)
    enc3_tc<2, false><<<148, ETROWS, encSmem>>>(
        nodes, enW0, enb0, enW1, enb1, enW2, enb2, p_n, NN);

    // edge encoder (tensor cores, fp16 out)
    enc3_tc<3, true><<<148, ETROWS, encSmem>>>(
        edges, eeW0, eeb0, eeW1, eeb1, eeW2, eeb2, p_elat, EE);

    // processor steps
    const int aggBlocks = (NN * 32 + 255) / 256;
    const int nodeSmem = WSTEP_U * 4;
    cudaFuncSetAttribute(node_mlp_tc,
                         cudaFuncAttributeMaxDynamicSharedMemorySize, nodeSmem);
    const int nodeBlocks = (NN + NTROWS - 1) / NTROWS;
    for (int s = 0; s < NSTEPS; s++) {
        agg_kernel<<<aggBlocks, 256>>>(p_n, p_x);
        node_mlp_tc<<<nodeBlocks, NTROWS, nodeSmem>>>(
            p_x, s,
            pb0 + (size_t)s * HH,
            pb1 + (size_t)s * HH,
            pb2 + (size_t)s * LL,
            p_n);
    }

    // decoder + mask (FFMA)
    mlp3_kernel<64, 2><<<(NN + 31) / 32, 256>>>(
        p_n, dW0, db0, dW1, db1, dW2, db2, out, NN, nodes);
}

// round 16
// speedup vs baseline: 1.3019x; 1.0191x over previous
#include <cuda_runtime.h>
#include <cuda_bf16.h>
#include <cuda_fp16.h>
#include <math.h>

#define NN 50000
#define EE 1250000
#define HH 128
#define LL 64
#define NSTEPS 5
#define EPSV 1e-6f
#define SMSHIFT 30.0f

#define ETROWS 256
#define NTROWS 256

#define W0F_U (4 * 16 * 32 * 4)
#define W1F_U (8 * 16 * 32 * 4)
#define W2F_U (8 * 8 * 32 * 4)
#define WSTEP_U (W0F_U + W1F_U + W2F_U)

// ---------------- device scratch ----------------
__device__ __half2 g_elat[(size_t)EE * 32];   // edge latents fp16 (160 MB)
__device__ float g_n[NN * LL];
__device__ float g_x[NN * LL];
__device__ int   g_deg[NN];
__device__ int   g_rowstart[NN + 1];
__device__ int   g_cursor[NN];
__device__ int2  g_epair[EE];                 // CSR slot -> (edge id, sender)
__device__ unsigned g_wfrag[NSTEPS * WSTEP_U];

// ---------------- CSR build ----------------
__global__ void degree_kernel(const int* __restrict__ receivers) {
    int e = blockIdx.x * blockDim.x + threadIdx.x;
    if (e < EE) atomicAdd(&g_deg[receivers[e]], 1);
}
__global__ void scan_kernel() {
    __shared__ int ssum[1024];
    const int tid = threadIdx.x;
    const int chunk = (NN + 1023) / 1024;
    const int start = tid * chunk;
    const int cend = min(start + chunk, NN);
    int sum = 0;
    for (int i = start; i < cend; i++) sum += g_deg[i];
    ssum[tid] = sum;
    __syncthreads();
    if (tid == 0) {
        int run = 0;
        for (int i = 0; i < 1024; i++) { int v = ssum[i]; ssum[i] = run; run += v; }
        g_rowstart[NN] = run;
    }
    __syncthreads();
    int run = ssum[tid];
    for (int i = start; i < cend; i++) {
        g_rowstart[i] = run;
        g_cursor[i] = run;
        run += g_deg[i];
    }
}
__global__ void scatter_kernel(const int* __restrict__ receivers,
                               const int* __restrict__ senders) {
    int e = blockIdx.x * blockDim.x + threadIdx.x;
    if (e < EE) {
        int r = receivers[e];
        int p = atomicAdd(&g_cursor[r], 1);
        g_epair[p] = make_int2(e, senders[e]);
    }
}

// ---------------- bf16 split + mma helpers ----------------
__device__ __forceinline__ void split2(float a, float b, unsigned& hi, unsigned& lo) {
    __nv_bfloat16 ha = __float2bfloat16(a);
    __nv_bfloat16 hb = __float2bfloat16(b);
    float la = a - __bfloat162float(ha);
    float lb = b - __bfloat162float(hb);
    __nv_bfloat162 ph; ph.x = ha; ph.y = hb;
    __nv_bfloat162 pl = __floats2bfloat162_rn(la, lb);
    hi = *(unsigned*)&ph;
    lo = *(unsigned*)&pl;
}

__device__ __forceinline__ void mma_bf16(float* d, uint4 a, uint2 b) {
    asm volatile(
        "mma.sync.aligned.m16n8k16.row.col.f32.bf16.bf16.f32 "
        "{%0,%1,%2,%3}, {%4,%5,%6,%7}, {%8,%9}, {%0,%1,%2,%3};\n"
        : "+f"(d[0]), "+f"(d[1]), "+f"(d[2]), "+f"(d[3])
        : "r"(a.x), "r"(a.y), "r"(a.z), "r"(a.w), "r"(b.x), "r"(b.y));
}

__device__ __forceinline__ void mma3(float* d, uint4 ah, uint4 al, uint4 q) {
    uint2 bh = make_uint2(q.x, q.y);
    uint2 bl = make_uint2(q.z, q.w);
    mma_bf16(d, ah, bh);
    mma_bf16(d, ah, bl);
    mma_bf16(d, al, bh);
}

__device__ __forceinline__ void stage_bfrag_g(
    const float* __restrict__ W, int ncols, int KT, int NT, unsigned* dst,
    int tid, int nthreads)
{
    int total = KT * NT * 64;
    for (int idx = tid; idx < total; idx += nthreads) {
        int reg = idx & 1;
        int ln  = (idx >> 1) & 31;
        int fnt = (idx >> 6) % NT;
        int fkt = (idx >> 6) / NT;
        int k = fkt * 16 + reg * 8 + (ln & 3) * 2;
        int n = fnt * 8 + (ln >> 2);
        unsigned hi, lo;
        split2(__ldg(W + k * ncols + n), __ldg(W + (k + 1) * ncols + n), hi, lo);
        unsigned* cell = dst + ((size_t)(fkt * NT + fnt) * 32 + ln) * 4;
        cell[reg]     = hi;
        cell[2 + reg] = lo;
    }
}

// grid (NSTEPS, CHUNKS): parallel weight-fragment conversion
#define PREP_CHUNKS 8
__global__ void prep_wfrag_kernel(const float* __restrict__ pW0,
                                  const float* __restrict__ pW1,
                                  const float* __restrict__ pW2)
{
    int s = blockIdx.x;
    int tid = blockIdx.y * blockDim.x + threadIdx.x;
    int nth = PREP_CHUNKS * blockDim.x;
    unsigned* dst = g_wfrag + (size_t)s * WSTEP_U;
    stage_bfrag_g(pW0 + (size_t)s * LL * HH, HH, 4, 16, dst, tid, nth);
    stage_bfrag_g(pW1 + (size_t)s * HH * HH, HH, 8, 16, dst + W0F_U, tid, nth);
    stage_bfrag_g(pW2 + (size_t)s * HH * LL, LL, 8, 8,  dst + W0F_U + W1F_U, tid, nth);
}

// ---------------- tensor-core 3-layer encoder: IN -> 128 -> 128 -> 64 ----------------
template <int IN, bool HALFOUT>
__global__ void __launch_bounds__(ETROWS, 1) enc3_tc(
    const float* __restrict__ Xin,
    const float* __restrict__ W0, const float* __restrict__ B0,
    const float* __restrict__ W1, const float* __restrict__ B1,
    const float* __restrict__ W2, const float* __restrict__ B2,
    void* __restrict__ Yout, int nrows)
{
    extern __shared__ unsigned smu[];
    unsigned* B1f = smu;
    unsigned* B2f = B1f + 8 * 16 * 32 * 4;

    const int tid  = threadIdx.x;
    const int lane = tid & 31;
    const int warp = tid >> 5;
    const int cbase = (lane & 3) * 2;

    stage_bfrag_g(W1, HH, 8, 16, B1f, tid, ETROWS);
    stage_bfrag_g(W2, LL, 8, 8,  B2f, tid, ETROWS);
    __syncthreads();

    float2 b1c[16], b2c[8];
#pragma unroll
    for (int nt = 0; nt < 16; nt++) b1c[nt] = __ldg((const float2*)(B1 + nt * 8 + cbase));
#pragma unroll
    for (int nt = 0; nt < 8;  nt++) b2c[nt] = __ldg((const float2*)(B2 + nt * 8 + cbase));

    const int ntiles = (nrows + ETROWS - 1) / ETROWS;
    for (int tile = blockIdx.x; tile < ntiles; tile += gridDim.x) {
        const int row0 = tile * ETROWS;
        const int rb = row0 + warp * 32 + (lane >> 2);

        float xr[4][IN];
#pragma unroll
        for (int j = 0; j < 4; j++) {
            int gr = rb + j * 8;
            bool ok = (gr < nrows);
            const float* p = Xin + (size_t)gr * IN;
#pragma unroll
            for (int c = 0; c < IN; c++) xr[j][c] = ok ? __ldg(p + c) : 0.f;
        }

        float acc1[2][16][4];
#pragma unroll
        for (int nt = 0; nt < 16; nt++) {
#pragma unroll
            for (int mt = 0; mt < 2; mt++) {
                acc1[mt][nt][0] = b1c[nt].x; acc1[mt][nt][1] = b1c[nt].y;
                acc1[mt][nt][2] = b1c[nt].x; acc1[mt][nt][3] = b1c[nt].y;
            }
        }
#pragma unroll
        for (int kt = 0; kt < 8; kt++) {
            float v[4][4];
#pragma unroll
            for (int cc = 0; cc < 4; cc++) {
                int col = kt * 16 + cbase + (cc & 1) + ((cc >> 1) << 3);
                float wv[IN];
#pragma unroll
                for (int c = 0; c < IN; c++) wv[c] = __ldg(W0 + c * HH + col);
                float bb = __ldg(B0 + col);
#pragma unroll
                for (int j = 0; j < 4; j++) {
                    float t = bb;
#pragma unroll
                    for (int c = 0; c < IN; c++) t = fmaf(xr[j][c], wv[c], t);
                    v[j][cc] = fmaxf(t, 0.f);
                }
            }
            uint4 AH[2], AL[2];
#pragma unroll
            for (int mt = 0; mt < 2; mt++) {
                split2(v[2 * mt][0],     v[2 * mt][1],     AH[mt].x, AL[mt].x);
                split2(v[2 * mt + 1][0], v[2 * mt + 1][1], AH[mt].y, AL[mt].y);
                split2(v[2 * mt][2],     v[2 * mt][3],     AH[mt].z, AL[mt].z);
                split2(v[2 * mt + 1][2], v[2 * mt + 1][3], AH[mt].w, AL[mt].w);
            }
#pragma unroll
            for (int nt = 0; nt < 16; nt++) {
                uint4 q = *(const uint4*)(B1f + ((size_t)(kt * 16 + nt) * 32 + lane) * 4);
                mma3(acc1[0][nt], AH[0], AL[0], q);
                mma3(acc1[1][nt], AH[1], AL[1], q);
            }
        }

        unsigned A2h[2][8][4], A2l[2][8][4];
#pragma unroll
        for (int mt = 0; mt < 2; mt++) {
#pragma unroll
            for (int nt = 0; nt < 16; nt++) {
                int kt2 = nt >> 1, half = (nt & 1) * 2;
                split2(fmaxf(acc1[mt][nt][0], 0.f), fmaxf(acc1[mt][nt][1], 0.f),
                       A2h[mt][kt2][half], A2l[mt][kt2][half]);
                split2(fmaxf(acc1[mt][nt][2], 0.f), fmaxf(acc1[mt][nt][3], 0.f),
                       A2h[mt][kt2][half + 1], A2l[mt][kt2][half + 1]);
            }
        }

        float acc2[2][8][4];
#pragma unroll
        for (int nt = 0; nt < 8; nt++) {
#pragma unroll
            for (int mt = 0; mt < 2; mt++) {
                acc2[mt][nt][0] = b2c[nt].x; acc2[mt][nt][1] = b2c[nt].y;
                acc2[mt][nt][2] = b2c[nt].x; acc2[mt][nt][3] = b2c[nt].y;
            }
        }
#pragma unroll
        for (int kt = 0; kt < 8; kt++) {
            uint4 a2h0 = make_uint4(A2h[0][kt][0], A2h[0][kt][1], A2h[0][kt][2], A2h[0][kt][3]);
            uint4 a2l0 = make_uint4(A2l[0][kt][0], A2l[0][kt][1], A2l[0][kt][2], A2l[0][kt][3]);
            uint4 a2h1 = make_uint4(A2h[1][kt][0], A2h[1][kt][1], A2h[1][kt][2], A2h[1][kt][3]);
            uint4 a2l1 = make_uint4(A2l[1][kt][0], A2l[1][kt][1], A2l[1][kt][2], A2l[1][kt][3]);
#pragma unroll
            for (int nt = 0; nt < 8; nt++) {
                uint4 q = *(const uint4*)(B2f + ((size_t)(kt * 8 + nt) * 32 + lane) * 4);
                mma3(acc2[0][nt], a2h0, a2l0, q);
                mma3(acc2[1][nt], a2h1, a2l1, q);
            }
        }

#pragma unroll
        for (int mt = 0; mt < 2; mt++) {
            int r0g = row0 + warp * 32 + mt * 16 + (lane >> 2);
            int r1g = r0g + 8;
#pragma unroll
            for (int nt = 0; nt < 8; nt++) {
                if (HALFOUT) {
                    __half2* Y = (__half2*)Yout;
                    int cid = nt * 4 + (lane & 3);
                    if (r0g < nrows)
                        Y[(size_t)r0g * 32 + cid] = __floats2half2_rn(acc2[mt][nt][0], acc2[mt][nt][1]);
                    if (r1g < nrows)
                        Y[(size_t)r1g * 32 + cid] = __floats2half2_rn(acc2[mt][nt][2], acc2[mt][nt][3]);
                } else {
                    float* Y = (float*)Yout;
                    int colg = nt * 8 + cbase;
                    if (r0g < nrows) {
                        float2 o; o.x = acc2[mt][nt][0]; o.y = acc2[mt][nt][1];
                        *(float2*)&Y[(size_t)r0g * LL + colg] = o;
                    }
                    if (r1g < nrows) {
                        float2 o; o.x = acc2[mt][nt][2]; o.y = acc2[mt][nt][3];
                        *(float2*)&Y[(size_t)r1g * LL + colg] = o;
                    }
                }
            }
        }
    }
}

// ---------------- tensor-core node-step MLP: 64 -> 128 -> 128 -> 64 ----------------
__global__ void __launch_bounds__(NTROWS, 1) node_mlp_tc(
    const float* __restrict__ X,
    int step,
    const float* __restrict__ B0,
    const float* __restrict__ B1,
    const float* __restrict__ B2,
    float* __restrict__ Y)
{
    extern __shared__ unsigned smu[];
    unsigned* W0f = smu;
    unsigned* W1f = W0f + W0F_U;
    unsigned* W2f = W1f + W1F_U;

    {
        const uint4* src = (const uint4*)(g_wfrag + (size_t)step * WSTEP_U);
        uint4* dst = (uint4*)smu;
        for (int i = threadIdx.x; i < WSTEP_U / 4; i += NTROWS) dst[i] = __ldg(src + i);
    }
    __syncthreads();

    const int lane = threadIdx.x & 31;
    const int warp = threadIdx.x >> 5;
    const int cbase = (lane & 3) * 2;
    const int g0 = blockIdx.x * NTROWS + warp * 32 + (lane >> 2);

    float acc1[2][16][4];
#pragma unroll
    for (int nt = 0; nt < 16; nt++) {
        float2 b = __ldg((const float2*)(B0 + nt * 8 + cbase));
#pragma unroll
        for (int mt = 0; mt < 2; mt++) {
            acc1[mt][nt][0] = b.x; acc1[mt][nt][1] = b.y;
            acc1[mt][nt][2] = b.x; acc1[mt][nt][3] = b.y;
        }
    }
#pragma unroll
    for (int kt = 0; kt < 4; kt++) {
        uint4 AH[2], AL[2];
#pragma unroll
        for (int mt = 0; mt < 2; mt++) {
            int ga = g0 + mt * 16, gb = ga + 8;
            float2 z = make_float2(0.f, 0.f);
            float2 p0 = (ga < NN) ? *(const float2*)(X + (size_t)ga * LL + kt * 16 + cbase)     : z;
            float2 p1 = (gb < NN) ? *(const float2*)(X + (size_t)gb * LL + kt * 16 + cbase)     : z;
            float2 p2 = (ga < NN) ? *(const float2*)(X + (size_t)ga * LL + kt * 16 + cbase + 8) : z;
            float2 p3 = (gb < NN) ? *(const float2*)(X + (size_t)gb * LL + kt * 16 + cbase + 8) : z;
            split2(p0.x, p0.y, AH[mt].x, AL[mt].x);
            split2(p1.x, p1.y, AH[mt].y, AL[mt].y);
            split2(p2.x, p2.y, AH[mt].z, AL[mt].z);
            split2(p3.x, p3.y, AH[mt].w, AL[mt].w);
        }
#pragma unroll
        for (int nt = 0; nt < 16; nt++) {
            uint4 q = *(const uint4*)(W0f + ((size_t)(kt * 16 + nt) * 32 + lane) * 4);
            mma3(acc1[0][nt], AH[0], AL[0], q);
            mma3(acc1[1][nt], AH[1], AL[1], q);
        }
    }

    unsigned A2h[2][8][4], A2l[2][8][4];
#pragma unroll
    for (int mt = 0; mt < 2; mt++) {
        unsigned A1h[8][4], A1l[8][4];
#pragma unroll
        for (int nt = 0; nt < 16; nt++) {
            int kt2 = nt >> 1, half = (nt & 1) * 2;
            split2(fmaxf(acc1[mt][nt][0], 0.f), fmaxf(acc1[mt][nt][1], 0.f),
                   A1h[kt2][half], A1l[kt2][half]);
            split2(fmaxf(acc1[mt][nt][2], 0.f), fmaxf(acc1[mt][nt][3], 0.f),
                   A1h[kt2][half + 1], A1l[kt2][half + 1]);
        }
        float accB[16][4];
#pragma unroll
        for (int nt = 0; nt < 16; nt++) {
            float2 b = __ldg((const float2*)(B1 + nt * 8 + cbase));
            accB[nt][0] = b.x; accB[nt][1] = b.y; accB[nt][2] = b.x; accB[nt][3] = b.y;
        }
#pragma unroll
        for (int kt = 0; kt < 8; kt++) {
            uint4 ah = make_uint4(A1h[kt][0], A1h[kt][1], A1h[kt][2], A1h[kt][3]);
            uint4 al = make_uint4(A1l[kt][0], A1l[kt][1], A1l[kt][2], A1l[kt][3]);
#pragma unroll
            for (int nt = 0; nt < 16; nt++) {
                uint4 q = *(const uint4*)(W1f + ((size_t)(kt * 16 + nt) * 32 + lane) * 4);
                mma3(accB[nt], ah, al, q);
            }
        }
#pragma unroll
        for (int nt = 0; nt < 16; nt++) {
            int kt2 = nt >> 1, half = (nt & 1) * 2;
            split2(fmaxf(accB[nt][0], 0.f), fmaxf(accB[nt][1], 0.f),
                   A2h[mt][kt2][half], A2l[mt][kt2][half]);
            split2(fmaxf(accB[nt][2], 0.f), fmaxf(accB[nt][3], 0.f),
                   A2h[mt][kt2][half + 1], A2l[mt][kt2][half + 1]);
        }
    }

    float acc2[2][8][4];
#pragma unroll
    for (int nt = 0; nt < 8; nt++) {
        float2 b = __ldg((const float2*)(B2 + nt * 8 + cbase));
#pragma unroll
        for (int mt = 0; mt < 2; mt++) {
            acc2[mt][nt][0] = b.x; acc2[mt][nt][1] = b.y;
            acc2[mt][nt][2] = b.x; acc2[mt][nt][3] = b.y;
        }
    }
#pragma unroll
    for (int kt = 0; kt < 8; kt++) {
        uint4 a2h0 = make_uint4(A2h[0][kt][0], A2h[0][kt][1], A2h[0][kt][2], A2h[0][kt][3]);
        uint4 a2l0 = make_uint4(A2l[0][kt][0], A2l[0][kt][1], A2l[0][kt][2], A2l[0][kt][3]);
        uint4 a2h1 = make_uint4(A2h[1][kt][0], A2h[1][kt][1], A2h[1][kt][2], A2h[1][kt][3]);
        uint4 a2l1 = make_uint4(A2l[1][kt][0], A2l[1][kt][1], A2l[1][kt][2], A2l[1][kt][3]);
#pragma unroll
        for (int nt = 0; nt < 8; nt++) {
            uint4 q = *(const uint4*)(W2f + ((size_t)(kt * 8 + nt) * 32 + lane) * 4);
            mma3(acc2[0][nt], a2h0, a2l0, q);
            mma3(acc2[1][nt], a2h1, a2l1, q);
        }
    }

#pragma unroll
    for (int mt = 0; mt < 2; mt++) {
        int ga = g0 + mt * 16, gb = ga + 8;
#pragma unroll
        for (int nt = 0; nt < 8; nt++) {
            int colg = nt * 8 + cbase;
            if (ga < NN) {
                float2 o; o.x = acc2[mt][nt][0]; o.y = acc2[mt][nt][1];
                *(float2*)&Y[(size_t)ga * LL + colg] = o;
            }
            if (gb < NN) {
                float2 o; o.x = acc2[mt][nt][2]; o.y = acc2[mt][nt][3];
                *(float2*)&Y[(size_t)gb * LL + colg] = o;
            }
        }
    }
}

// ---------------- tensor-core decoder: 64 -> 128 -> 128 -> 2 (+ mask) ----------------
__global__ void __launch_bounds__(NTROWS, 1) decoder_tc(
    const float* __restrict__ X,
    const float* __restrict__ W0, const float* __restrict__ B0,
    const float* __restrict__ W1, const float* __restrict__ B1,
    const float* __restrict__ W2, const float* __restrict__ B2,
    const float* __restrict__ mask_src,
    float* __restrict__ out)
{
    extern __shared__ unsigned smu[];
    unsigned* W0f = smu;                 // 4*16*32*4
    unsigned* W1f = W0f + W0F_U;         // 8*16*32*4

    stage_bfrag_g(W0, HH, 4, 16, W0f, threadIdx.x, NTROWS);
    stage_bfrag_g(W1, HH, 8, 16, W1f, threadIdx.x, NTROWS);
    __syncthreads();

    const int lane = threadIdx.x & 31;
    const int warp = threadIdx.x >> 5;
    const int cbase = (lane & 3) * 2;
    const int g0 = blockIdx.x * NTROWS + warp * 32 + (lane >> 2);

    // layer 0: 64 -> 128 (identical to node_mlp_tc)
    float acc1[2][16][4];
#pragma unroll
    for (int nt = 0; nt < 16; nt++) {
        float2 b = __ldg((const float2*)(B0 + nt * 8 + cbase));
#pragma unroll
        for (int mt = 0; mt < 2; mt++) {
            acc1[mt][nt][0] = b.x; acc1[mt][nt][1] = b.y;
            acc1[mt][nt][2] = b.x; acc1[mt][nt][3] = b.y;
        }
    }
#pragma unroll
    for (int kt = 0; kt < 4; kt++) {
        uint4 AH[2], AL[2];
#pragma unroll
        for (int mt = 0; mt < 2; mt++) {
            int ga = g0 + mt * 16, gb = ga + 8;
            float2 z = make_float2(0.f, 0.f);
            float2 p0 = (ga < NN) ? *(const float2*)(X + (size_t)ga * LL + kt * 16 + cbase)     : z;
            float2 p1 = (gb < NN) ? *(const float2*)(X + (size_t)gb * LL + kt * 16 + cbase)     : z;
            float2 p2 = (ga < NN) ? *(const float2*)(X + (size_t)ga * LL + kt * 16 + cbase + 8) : z;
            float2 p3 = (gb < NN) ? *(const float2*)(X + (size_t)gb * LL + kt * 16 + cbase + 8) : z;
            split2(p0.x, p0.y, AH[mt].x, AL[mt].x);
            split2(p1.x, p1.y, AH[mt].y, AL[mt].y);
            split2(p2.x, p2.y, AH[mt].z, AL[mt].z);
            split2(p3.x, p3.y, AH[mt].w, AL[mt].w);
        }
#pragma unroll
        for (int nt = 0; nt < 16; nt++) {
            uint4 q = *(const uint4*)(W0f + ((size_t)(kt * 16 + nt) * 32 + lane) * 4);
            mma3(acc1[0][nt], AH[0], AL[0], q);
            mma3(acc1[1][nt], AH[1], AL[1], q);
        }
    }

    const float bo0 = __ldg(B2);
    const float bo1 = __ldg(B2 + 1);

    // layer 1 per mt, then scalar layer-2 epilogue (OUT=2) with quad reduction
#pragma unroll
    for (int mt = 0; mt < 2; mt++) {
        unsigned A1h[8][4], A1l[8][4];
#pragma unroll
        for (int nt = 0; nt < 16; nt++) {
            int kt2 = nt >> 1, half = (nt & 1) * 2;
            split2(fmaxf(acc1[mt][nt][0], 0.f), fmaxf(acc1[mt][nt][1], 0.f),
                   A1h[kt2][half], A1l[kt2][half]);
            split2(fmaxf(acc1[mt][nt][2], 0.f), fmaxf(acc1[mt][nt][3], 0.f),
                   A1h[kt2][half + 1], A1l[kt2][half + 1]);
        }
        float accB[16][4];
#pragma unroll
        for (int nt = 0; nt < 16; nt++) {
            float2 b = __ldg((const float2*)(B1 + nt * 8 + cbase));
            accB[nt][0] = b.x; accB[nt][1] = b.y; accB[nt][2] = b.x; accB[nt][3] = b.y;
        }
#pragma unroll
        for (int kt = 0; kt < 8; kt++) {
            uint4 ah = make_uint4(A1h[kt][0], A1h[kt][1], A1h[kt][2], A1h[kt][3]);
            uint4 al = make_uint4(A1l[kt][0], A1l[kt][1], A1l[kt][2], A1l[kt][3]);
#pragma unroll
            for (int nt = 0; nt < 16; nt++) {
                uint4 q = *(const uint4*)(W1f + ((size_t)(kt * 16 + nt) * 32 + lane) * 4);
                mma3(accB[nt], ah, al, q);
            }
        }

        // layer 2: out[r][o] = b2[o] + sum_k relu(h2[r][k]) * W2[k][o]
        // each lane holds cols {nt*8+cbase, +1} of rows (ga, gb): partial + quad shfl reduce
        float pa0 = 0.f, pa1 = 0.f, pb0 = 0.f, pb1 = 0.f;
#pragma unroll
        for (int nt = 0; nt < 16; nt++) {
            int c0 = nt * 8 + cbase;
            float w00 = __ldg(W2 + c0 * 2);
            float w01 = __ldg(W2 + c0 * 2 + 1);
            float w10 = __ldg(W2 + (c0 + 1) * 2);
            float w11 = __ldg(W2 + (c0 + 1) * 2 + 1);
            float h0 = fmaxf(accB[nt][0], 0.f);
            float h1 = fmaxf(accB[nt][1], 0.f);
            float h2 = fmaxf(accB[nt][2], 0.f);
            float h3 = fmaxf(accB[nt][3], 0.f);
            pa0 = fmaf(h0, w00, fmaf(h1, w10, pa0));
            pa1 = fmaf(h0, w01, fmaf(h1, w11, pa1));
            pb0 = fmaf(h2, w00, fmaf(h3, w10, pb0));
            pb1 = fmaf(h2, w01, fmaf(h3, w11, pb1));
        }
        // reduce across the 4 lanes of the quad (xor 1 and 2 stay in-quad)
        pa0 += __shfl_xor_sync(0xffffffff, pa0, 1); pa0 += __shfl_xor_sync(0xffffffff, pa0, 2);
        pa1 += __shfl_xor_sync(0xffffffff, pa1, 1); pa1 += __shfl_xor_sync(0xffffffff, pa1, 2);
        pb0 += __shfl_xor_sync(0xffffffff, pb0, 1); pb0 += __shfl_xor_sync(0xffffffff, pb0, 2);
        pb1 += __shfl_xor_sync(0xffffffff, pb1, 1); pb1 += __shfl_xor_sync(0xffffffff, pb1, 2);

        if ((lane & 3) == 0) {
            int ga = g0 + mt * 16, gb = ga + 8;
            if (ga < NN) {
                float mk = ((fabsf(__ldg(mask_src + ga * 2)) +
                             fabsf(__ldg(mask_src + ga * 2 + 1))) != 0.f) ? 1.f : 0.f;
                out[(size_t)ga * 2]     = (pa0 + bo0) * mk;
                out[(size_t)ga * 2 + 1] = (pa1 + bo1) * mk;
            }
            if (gb < NN) {
                float mk = ((fabsf(__ldg(mask_src + gb * 2)) +
                             fabsf(__ldg(mask_src + gb * 2 + 1))) != 0.f) ? 1.f : 0.f;
                out[(size_t)gb * 2]     = (pb0 + bo0) * mk;
                out[(size_t)gb * 2 + 1] = (pb1 + bo1) * mk;
            }
        }
    }
}

// ---------------- softmax aggregation: fp16 elat, fp32 nin, simple 8-wide strip ----------------
__global__ void __launch_bounds__(256) agg_kernel(
    const float* __restrict__ nin,
    float* __restrict__ xout)
{
    const int gw = (blockIdx.x * blockDim.x + threadIdx.x) >> 5;
    if (gw >= NN) return;
    const int lane = threadIdx.x & 31;
    const int beg = __ldg(g_rowstart + gw);
    const int end = __ldg(g_rowstart + gw + 1);

    const float2* nin2 = (const float2*)nin;
    float S0 = 0.f, S1 = 0.f, A0 = 0.f, A1 = 0.f;

    int idx = beg;
    for (; idx + 8 <= end; idx += 8) {
        int2 pr[8];
#pragma unroll
        for (int u = 0; u < 8; u++) pr[u] = __ldg(g_epair + idx + u);
        float2 ev[8], nv[8];
#pragma unroll
        for (int u = 0; u < 8; u++)
            ev[u] = __half22float2(__ldg(g_elat + (size_t)pr[u].x * 32 + lane));
#pragma unroll
        for (int u = 0; u < 8; u++) nv[u] = __ldg(nin2 + (size_t)pr[u].y * 32 + lane);
#pragma unroll
        for (int u = 0; u < 8; u++) {
            float m0 = fmaxf(ev[u].x + nv[u].x, 0.f) + EPSV;
            float m1 = fmaxf(ev[u].y + nv[u].y, 0.f) + EPSV;
            float t0 = __expf(m0 - SMSHIFT);
            float t1 = __expf(m1 - SMSHIFT);
            S0 += t0; A0 = fmaf(t0, m0, A0);
            S1 += t1; A1 = fmaf(t1, m1, A1);
        }
    }
    for (; idx < end; idx++) {
        int2 pr = __ldg(g_epair + idx);
        float2 ea = __half22float2(__ldg(g_elat + (size_t)pr.x * 32 + lane));
        float2 na = __ldg(nin2 + (size_t)pr.y * 32 + lane);
        float m0 = fmaxf(ea.x + na.x, 0.f) + EPSV;
        float m1 = fmaxf(ea.y + na.y, 0.f) + EPSV;
        float t0 = __expf(m0 - SMSHIFT);
        float t1 = __expf(m1 - SMSHIFT);
        S0 += t0; A0 = fmaf(t0, m0, A0);
        S1 += t1; A1 = fmaf(t1, m1, A1);
    }

    float r0 = (S0 > 0.f) ? A0 / S0 : 0.f;
    float r1 = (S1 > 0.f) ? A1 / S1 : 0.f;
    float2 ns = __ldg(nin2 + (size_t)gw * 32 + lane);
    float2 o; o.x = ns.x + r0; o.y = ns.y + r1;
    *((float2*)xout + (size_t)gw * 32 + lane) = o;
}

// ---------------- launch ----------------
extern "C" void kernel_launch(void* const* d_in, const int* in_sizes, int n_in,
                              void* d_out, int out_size)
{
    const float* nodes     = (const float*)d_in[0];
    const float* edges     = (const float*)d_in[1];
    const int*   senders   = (const int*)  d_in[2];
    const int*   receivers = (const int*)  d_in[3];
    const float* enW0 = (const float*)d_in[4];  const float* enb0 = (const float*)d_in[5];
    const float* enW1 = (const float*)d_in[6];  const float* enb1 = (const float*)d_in[7];
    const float* enW2 = (const float*)d_in[8];  const float* enb2 = (const float*)d_in[9];
    const float* eeW0 = (const float*)d_in[10]; const float* eeb0 = (const float*)d_in[11];
    const float* eeW1 = (const float*)d_in[12]; const float* eeb1 = (const float*)d_in[13];
    const float* eeW2 = (const float*)d_in[14]; const float* eeb2 = (const float*)d_in[15];
    const float* pW0  = (const float*)d_in[16]; const float* pb0  = (const float*)d_in[17];
    const float* pW1  = (const float*)d_in[18]; const float* pb1  = (const float*)d_in[19];
    const float* pW2  = (const float*)d_in[20]; const float* pb2  = (const float*)d_in[21];
    const float* dW0  = (const float*)d_in[22]; const float* db0  = (const float*)d_in[23];
    const float* dW1  = (const float*)d_in[24]; const float* db1  = (const float*)d_in[25];
    const float* dW2  = (const float*)d_in[26]; const float* db2  = (const float*)d_in[27];
    float* out = (float*)d_out;

    __half2* p_elat = nullptr;
    float *p_n = nullptr, *p_x = nullptr;
    int* p_deg = nullptr;
    cudaGetSymbolAddress((void**)&p_elat, g_elat);
    cudaGetSymbolAddress((void**)&p_n,    g_n);
    cudaGetSymbolAddress((void**)&p_x,    g_x);
    cudaGetSymbolAddress((void**)&p_deg,  g_deg);

    // CSR build
    cudaMemsetAsync(p_deg, 0, NN * sizeof(int));
    degree_kernel<<<(EE + 255) / 256, 256>>>(receivers);
    scan_kernel<<<1, 1024>>>();
    scatter_kernel<<<(EE + 255) / 256, 256>>>(receivers, senders);

    // pre-convert step-MLP weights (parallel)
    {
        dim3 pgrid(NSTEPS, PREP_CHUNKS);
        prep_wfrag_kernel<<<pgrid, 256>>>(pW0, pW1, pW2);
    }

    const int encSmem = (8 * 16 * 32 * 4 + 8 * 8 * 32 * 4) * 4;
    cudaFuncSetAttribute(enc3_tc<2, false>,
                         cudaFuncAttributeMaxDynamicSharedMemorySize, encSmem);
    cudaFuncSetAttribute(enc3_tc<3, true>,
                         cudaFuncAttributeMaxDynamicSharedMemorySize, encSmem);

    // node encoder (tensor cores, fp32 out)
    enc3_tc<2, false><<<148, ETROWS, encSmem>>>(
        nodes, enW0, enb0, enW1, enb1, enW2, enb2, p_n, NN);

    // edge encoder (tensor cores, fp16 out)
    enc3_tc<3, true><<<148, ETROWS, encSmem>>>(
        edges, eeW0, eeb0, eeW1, eeb1, eeW2, eeb2, p_elat, EE);

    // processor steps
    const int aggBlocks = (NN * 32 + 255) / 256;
    const int nodeSmem = WSTEP_U * 4;
    cudaFuncSetAttribute(node_mlp_tc,
                         cudaFuncAttributeMaxDynamicSharedMemorySize, nodeSmem);
    const int nodeBlocks = (NN + NTROWS - 1) / NTROWS;
    for (int s = 0; s < NSTEPS; s++) {
        agg_kernel<<<aggBlocks, 256>>>(p_n, p_x);
        node_mlp_tc<<<nodeBlocks, NTROWS, nodeSmem>>>(
            p_x, s,
            pb0 + (size_t)s * HH,
            pb1 + (size_t)s * HH,
            pb2 + (size_t)s * LL,
            p_n);
    }

    // decoder + mask (tensor cores)
    {
        const int decSmem = (W0F_U + W1F_U) * 4;
        cudaFuncSetAttribute(decoder_tc,
                             cudaFuncAttributeMaxDynamicSharedMemorySize, decSmem);
        decoder_tc<<<nodeBlocks, NTROWS, decSmem>>>(
            p_n, dW0, db0, dW1, db1, dW2, db2, nodes, out);
    }
}